// round 3
// baseline (speedup 1.0000x reference)
#include <cuda_runtime.h>

#define NB 8
#define NN 64
#define NT 50
#define TO 49      // output timesteps (t = NT-1 never needed)
#define ND 4
#define NH 64
#define EPN 63     // real edges per recv node (slot 63 is a dummy, rt=0)
#define NNODES (NB * TO * NN)     // 25088
#define EDGE_GRID 296             // 148 SMs x 2 CTAs

// Scratch (static __device__ — no allocation in kernel_launch)
__device__ float g_u[NB * TO * NN * NH];   // u' = W1r @ x + b1   (per node)
__device__ float g_v[NB * TO * NN * NH];   // v  = W1s @ x        (per node)
__device__ float g_w2t[NH * NH];           // fc2_w[1] transposed: [k][j]

// ---------------------------------------------------------------------------
// packed f32x2 helpers
__device__ __forceinline__ unsigned long long pack_dup(float x) {
    unsigned long long r;
    unsigned int u = __float_as_uint(x);
    asm("mov.b64 %0, {%1, %1};" : "=l"(r) : "r"(u));
    return r;
}
__device__ __forceinline__ void fma2(unsigned long long& d,
                                     unsigned long long a,
                                     unsigned long long b) {
    asm("fma.rn.f32x2 %0, %1, %2, %0;" : "+l"(d) : "l"(a), "l"(b));
}
__device__ __forceinline__ void unpack2(unsigned long long v, float& lo, float& hi) {
    unsigned int a, b;
    asm("mov.b64 {%0, %1}, %2;" : "=r"(a), "=r"(b) : "l"(v));
    lo = __uint_as_float(a);
    hi = __uint_as_float(b);
}

// ---------------------------------------------------------------------------
// Kernel 1: per-node fc1 factorization + (first 4096 threads) W2 transpose.
__global__ void k_node_embed(const float* __restrict__ inputs,
                             const float* __restrict__ fc1_w,
                             const float* __restrict__ fc1_b,
                             const float* __restrict__ fc2_w) {
    int gid = blockIdx.x * blockDim.x + threadIdx.x;
    if (gid < NH * NH) {
        int j = gid >> 6;
        int k = gid & 63;
        g_w2t[k * NH + j] = fc2_w[NH * NH + j * NH + k];   // fc2_w[1][j][k]
    }
    if (gid >= NB * TO * NN * NH) return;
    int h    = gid & 63;
    int node = gid >> 6;              // ((b*49 + t)*64 + n)
    int n    = node & 63;
    int bt   = node >> 6;
    int t    = bt % TO;
    int b    = bt / TO;

    const float* x = inputs + (((size_t)b * NN + n) * NT + t) * ND;
    const float* w = fc1_w + NH * 2 * ND + h * 2 * ND;   // fc1_w[1][h][:]
    float u = fc1_b[NH + h];
    float v = 0.f;
#pragma unroll
    for (int d = 0; d < ND; d++) {
        u += w[d] * x[d];
        v += w[ND + d] * x[d];
    }
    g_u[gid] = u;
    g_v[gid] = v;
}

// ---------------------------------------------------------------------------
// Kernel 2: PERSISTENT fused edge MLP (fc2, register-blocked f32x2) +
// aggregation + node MLP. 296 blocks x 128 threads; W2 loaded into registers
// ONCE per block, then the block loops over ~85 (b,t,recv) nodes.
__global__ void __launch_bounds__(128)
k_edge(const float* __restrict__ inputs,
       const float* __restrict__ rel_type,
       const float* __restrict__ fc2_b,
       const float* __restrict__ out1_w, const float* __restrict__ out1_b,
       const float* __restrict__ out2_w, const float* __restrict__ out2_b,
       const float* __restrict__ out3_w, const float* __restrict__ out3_b,
       float* __restrict__ out) {
    __shared__ unsigned long long h2_s[32 * NH];  // [epair][k] -> (h_e0, h_e1)
    __shared__ float u_s[NH];
    __shared__ float rt_s[64];
    __shared__ float red_s[4 * NH];
    __shared__ float agg_s[NH];
    __shared__ float m1_s[NH];
    __shared__ float m2_s[NH];
    __shared__ float x_s[ND];

    const int tid  = threadIdx.x;
    const int lane = tid & 31;
    const int warp = tid >> 5;

    // W2 into registers, ONCE: lane owns output cols (lane) and (lane+32).
    float wA[NH], wB[NH];
#pragma unroll
    for (int k = 0; k < NH; k++) {
        wA[k] = g_w2t[k * NH + lane];
        wB[k] = g_w2t[k * NH + lane + 32];
    }
    const float bjA = fc2_b[NH + lane];
    const float bjB = fc2_b[NH + lane + 32];

    for (int node = blockIdx.x; node < NNODES; node += EDGE_GRID) {
        const int n  = node & 63;
        const int bt = node >> 6;
        const int t  = bt % TO;
        const int b  = bt / TO;

        __syncthreads();   // previous iteration's smem reads complete

        if (tid < NH) u_s[tid] = g_u[(size_t)node * NH + tid];
        if (tid < 64) {
            float r = 0.f;
            if (tid < EPN)
                r = rel_type[((size_t)b * (NN * EPN) + n * EPN + tid) * 2 + 1];
            rt_s[tid] = r;
        }
        if (tid < ND) x_s[tid] = inputs[(((size_t)b * NN + n) * NT + t) * ND + tid];
        __syncthreads();

        // Stage h = relu(u[recv] + v[send]) for this warp's 16 slots,
        // interleaved by edge-pair: hf[(ep*NH + k)*2 + (s&1)].
        {
            const float* vbase = g_v + (size_t)(bt * NN) * NH;
            float* hf = (float*)h2_s;
            const float ua = u_s[lane];
            const float ub = u_s[lane + 32];
#pragma unroll
            for (int i = 0; i < 16; i++) {
                int s = warp * 16 + i;
                int send = (s >= EPN) ? n : (s + (s >= n ? 1 : 0));
                const float* v = vbase + send * NH;
                float ha = fmaxf(ua + v[lane],      0.f);
                float hb = fmaxf(ub + v[lane + 32], 0.f);
                int ep = s >> 1, eo = s & 1;
                hf[(ep * NH + lane) * 2 + eo]      = ha;
                hf[(ep * NH + lane + 32) * 2 + eo] = hb;
            }
        }
        __syncwarp();   // each warp reads only its own epairs

        // Main fc2: 8 edge-pairs, packed f32x2 accumulators.
        unsigned long long accA[8], accB[8];
#pragma unroll
        for (int p = 0; p < 8; p++) { accA[p] = 0ull; accB[p] = 0ull; }

        const unsigned long long* h2w = h2_s + (size_t)warp * 8 * NH;
#pragma unroll
        for (int k = 0; k < NH; k++) {
            unsigned long long wa = pack_dup(wA[k]);
            unsigned long long wb = pack_dup(wB[k]);
#pragma unroll
            for (int p = 0; p < 8; p++) {
                unsigned long long hp = h2w[p * NH + k];   // broadcast LDS.64
                fma2(accA[p], wa, hp);
                fma2(accB[p], wb, hp);
            }
        }

        // Epilogue: bias + relu + rt weighting, reduce over this warp's edges.
        float aggA = 0.f, aggB = 0.f;
#pragma unroll
        for (int p = 0; p < 8; p++) {
            int e0 = warp * 16 + p * 2;
            float r0 = rt_s[e0], r1 = rt_s[e0 + 1];
            float a0, a1, c0, c1;
            unpack2(accA[p], a0, a1);
            unpack2(accB[p], c0, c1);
            aggA += fmaxf(a0 + bjA, 0.f) * r0 + fmaxf(a1 + bjA, 0.f) * r1;
            aggB += fmaxf(c0 + bjB, 0.f) * r0 + fmaxf(c1 + bjB, 0.f) * r1;
        }
        red_s[warp * NH + lane]      = aggA;
        red_s[warp * NH + lane + 32] = aggB;
        __syncthreads();

        if (tid < NH)
            agg_s[tid] = red_s[tid] + red_s[NH + tid] + red_s[2 * NH + tid] + red_s[3 * NH + tid];
        __syncthreads();

        // Node MLP: aug = [x (4), agg (64)]
        if (tid < NH) {
            const float* w = out1_w + tid * (ND + NH);
            float acc = out1_b[tid];
#pragma unroll
            for (int d = 0; d < ND; d++) acc += w[d] * x_s[d];
#pragma unroll
            for (int k = 0; k < NH; k++) acc += w[ND + k] * agg_s[k];
            m1_s[tid] = fmaxf(acc, 0.f);
        }
        __syncthreads();
        if (tid < NH) {
            const float* w = out2_w + tid * NH;
            float acc = out2_b[tid];
#pragma unroll
            for (int k = 0; k < NH; k++) acc += w[k] * m1_s[k];
            m2_s[tid] = fmaxf(acc, 0.f);
        }
        __syncthreads();
        if (tid < ND) {
            const float* w = out3_w + tid * NH;
            float acc = out3_b[tid];
#pragma unroll
            for (int k = 0; k < NH; k++) acc += w[k] * m2_s[k];
            out[(((size_t)b * NN + n) * TO + t) * ND + tid] = x_s[tid] + acc;
        }
    }
}

// ---------------------------------------------------------------------------
extern "C" void kernel_launch(void* const* d_in, const int* in_sizes, int n_in,
                              void* d_out, int out_size) {
    const float* inputs   = (const float*)d_in[0];
    const float* rel_type = (const float*)d_in[1];
    // d_in[2] rel_rec, d_in[3] rel_send: one-hot by construction; indices analytic
    const float* fc1_w    = (const float*)d_in[4];
    const float* fc1_b    = (const float*)d_in[5];
    const float* fc2_w    = (const float*)d_in[6];
    const float* fc2_b    = (const float*)d_in[7];
    const float* out1_w   = (const float*)d_in[8];
    const float* out1_b   = (const float*)d_in[9];
    const float* out2_w   = (const float*)d_in[10];
    const float* out2_b   = (const float*)d_in[11];
    const float* out3_w   = (const float*)d_in[12];
    const float* out3_b   = (const float*)d_in[13];
    float* out = (float*)d_out;

    const int n_embed = NB * TO * NN * NH;
    k_node_embed<<<(n_embed + 255) / 256, 256>>>(inputs, fc1_w, fc1_b, fc2_w);

    k_edge<<<EDGE_GRID, 128>>>(inputs, rel_type, fc2_b,
                               out1_w, out1_b, out2_w, out2_b,
                               out3_w, out3_b, out);
}

// round 4
// speedup vs baseline: 1.1067x; 1.1067x over previous
#include <cuda_runtime.h>

#define NB 8
#define NN 64
#define NT 50
#define TO 49      // output timesteps (t = NT-1 never needed)
#define ND 4
#define NH 64
#define EPN 63     // real edges per recv node (slot 63 is a dummy, rt=0)
#define NNODES (NB * TO * NN)     // 25088
#define EDGE_GRID 296             // 148 SMs x 2 CTAs

typedef unsigned long long u64;

// Scratch (static __device__ — no allocation in kernel_launch)
__device__ float g_u[NB * TO * NN * NH];   // u' = W1r @ x + b1   (per node)
__device__ float g_v[NB * TO * NN * NH];   // v  = W1s @ x        (per node)
__device__ float g_w2t[NH * NH];           // fc2_w[1] transposed: [k][j]

// ---------------------------------------------------------------------------
// packed f32x2 helpers
__device__ __forceinline__ u64 pack_dup(float x) {
    u64 r;
    unsigned int u = __float_as_uint(x);
    asm("mov.b64 %0, {%1, %1};" : "=l"(r) : "r"(u));
    return r;
}
__device__ __forceinline__ u64 pack2(float lo, float hi) {
    u64 r;
    asm("mov.b64 %0, {%1, %2};" : "=l"(r) : "r"(__float_as_uint(lo)), "r"(__float_as_uint(hi)));
    return r;
}
__device__ __forceinline__ void fma2(u64& d, u64 a, u64 b) {
    asm("fma.rn.f32x2 %0, %1, %2, %0;" : "+l"(d) : "l"(a), "l"(b));
}
__device__ __forceinline__ u64 add2(u64 a, u64 b) {
    u64 r;
    asm("add.rn.f32x2 %0, %1, %2;" : "=l"(r) : "l"(a), "l"(b));
    return r;
}
__device__ __forceinline__ void unpack2(u64 v, float& lo, float& hi) {
    unsigned int a, b;
    asm("mov.b64 {%0, %1}, %2;" : "=r"(a), "=r"(b) : "l"(v));
    lo = __uint_as_float(a);
    hi = __uint_as_float(b);
}

// ---------------------------------------------------------------------------
// Kernel 1: per-node fc1 factorization + (first 4096 threads) W2 transpose.
__global__ void k_node_embed(const float* __restrict__ inputs,
                             const float* __restrict__ fc1_w,
                             const float* __restrict__ fc1_b,
                             const float* __restrict__ fc2_w) {
    int gid = blockIdx.x * blockDim.x + threadIdx.x;
    if (gid < NH * NH) {
        int j = gid >> 6;
        int k = gid & 63;
        g_w2t[k * NH + j] = fc2_w[NH * NH + j * NH + k];   // fc2_w[1][j][k]
    }
    if (gid >= NB * TO * NN * NH) return;
    int h    = gid & 63;
    int node = gid >> 6;              // ((b*49 + t)*64 + n)
    int n    = node & 63;
    int bt   = node >> 6;
    int t    = bt % TO;
    int b    = bt / TO;

    const float* x = inputs + (((size_t)b * NN + n) * NT + t) * ND;
    const float* w = fc1_w + NH * 2 * ND + h * 2 * ND;   // fc1_w[1][h][:]
    float u = fc1_b[NH + h];
    float v = 0.f;
#pragma unroll
    for (int d = 0; d < ND; d++) {
        u += w[d] * x[d];
        v += w[ND + d] * x[d];
    }
    g_u[gid] = u;
    g_v[gid] = v;
}

// ---------------------------------------------------------------------------
// Kernel 2: PERSISTENT fused edge MLP + aggregation + node MLP.
// 296 blocks x 256 threads (8 warps). Warp w = (group g = w>>1, k-half kh = w&1).
// Group g owns edge-pairs [8g, 8g+8) (16 slots); warp holds W2 slice
// [kh*32 .. kh*32+32) x {lane, lane+32} in 64 registers (no spills).
// h staged per-warp in smem (warp reads only what it wrote -> __syncwarp).
// k-half partials combined through a smem stash.
__global__ void __launch_bounds__(256, 2)
k_edge(const float* __restrict__ inputs,
       const float* __restrict__ rel_type,
       const float* __restrict__ fc2_b,
       const float* __restrict__ out1_w, const float* __restrict__ out1_b,
       const float* __restrict__ out2_w, const float* __restrict__ out2_b,
       const float* __restrict__ out3_w, const float* __restrict__ out3_b,
       float* __restrict__ out) {
    __shared__ u64 h2_s[32 * NH];        // [pair][k] -> (h_e0[k], h_e1[k])  16KB
    __shared__ u64 stash_s[4 * 8 * 2 * 32];  // [g][p][A/B][lane]            16KB
    __shared__ float u_s[NH];
    __shared__ float rt_s[64];
    __shared__ float red_s[4 * NH];
    __shared__ float agg_s[NH];
    __shared__ float m1_s[NH];
    __shared__ float m2_s[NH];
    __shared__ float x_s[ND];

    const int tid  = threadIdx.x;
    const int lane = tid & 31;
    const int warp = tid >> 5;
    const int g    = warp >> 1;          // pair-group 0..3
    const int kh   = warp & 1;           // k-half
    const int kbase = kh * 32;
    const int kmy   = kbase + lane;      // this lane's k-row for staging

    // W2 slice into registers, ONCE. 64 regs.
    float wA[32], wB[32];
#pragma unroll
    for (int k = 0; k < 32; k++) {
        wA[k] = g_w2t[(kbase + k) * NH + lane];
        wB[k] = g_w2t[(kbase + k) * NH + lane + 32];
    }
    const float bjA = fc2_b[NH + lane];
    const float bjB = fc2_b[NH + lane + 32];

    for (int node = blockIdx.x; node < NNODES; node += EDGE_GRID) {
        const int n  = node & 63;
        const int bt = node >> 6;
        const int t  = bt % TO;
        const int b  = bt / TO;

        __syncthreads();   // previous iteration's smem consumers done

        if (tid < 64) {
            u_s[tid] = g_u[(size_t)node * NH + tid];
            float r = 0.f;
            if (tid < EPN)
                r = rel_type[((size_t)b * (NN * EPN) + n * EPN + tid) * 2 + 1];
            rt_s[tid] = r;
        }
        if (tid < ND) x_s[tid] = inputs[(((size_t)b * NN + n) * NT + t) * ND + tid];
        __syncthreads();

        // Stage h = relu(u + v[send]) for this warp's 8 pairs at its k-row.
        {
            const float* vbase = g_v + (size_t)(bt * NN) * NH;
            const float ua = u_s[kmy];
#pragma unroll
            for (int p = 0; p < 8; p++) {
                const int s0 = (g * 8 + p) * 2;
                const int s1 = s0 + 1;
                const int send0 = s0 + (s0 >= n ? 1 : 0);           // s0 <= 62 < EPN
                const int send1 = (s1 >= EPN) ? n : (s1 + (s1 >= n ? 1 : 0));
                float ha = fmaxf(ua + vbase[send0 * NH + kmy], 0.f);
                float hb = fmaxf(ua + vbase[send1 * NH + kmy], 0.f);
                h2_s[(g * 8 + p) * NH + kmy] = pack2(ha, hb);
            }
        }
        __syncwarp();   // warp reads only its own writes

        // Inner fc2: 8 edge-pairs x 32 k, packed f32x2.
        u64 accA[8], accB[8];
#pragma unroll
        for (int p = 0; p < 8; p++) { accA[p] = 0ull; accB[p] = 0ull; }

        const u64* hbase = h2_s + (size_t)g * 8 * NH + kbase;
#pragma unroll
        for (int k = 0; k < 32; k++) {
            u64 wa = pack_dup(wA[k]);
            u64 wb = pack_dup(wB[k]);
#pragma unroll
            for (int p = 0; p < 8; p++) {
                u64 hp = hbase[p * NH + k];   // broadcast LDS.64
                fma2(accA[p], wa, hp);
                fma2(accB[p], wb, hp);
            }
        }

        // kh=1 warps stash partials; kh=0 warps combine + epilogue.
        if (kh == 1) {
            u64* st = stash_s + (size_t)g * 512;
#pragma unroll
            for (int p = 0; p < 8; p++) {
                st[(p * 2 + 0) * 32 + lane] = accA[p];
                st[(p * 2 + 1) * 32 + lane] = accB[p];
            }
        }
        __syncthreads();
        if (kh == 0) {
            const u64* st = stash_s + (size_t)g * 512;
            float aggA = 0.f, aggB = 0.f;
#pragma unroll
            for (int p = 0; p < 8; p++) {
                u64 tA = add2(accA[p], st[(p * 2 + 0) * 32 + lane]);
                u64 tB = add2(accB[p], st[(p * 2 + 1) * 32 + lane]);
                const int s0 = (g * 8 + p) * 2;
                float r0 = rt_s[s0], r1 = rt_s[s0 + 1];
                float a0, a1, c0, c1;
                unpack2(tA, a0, a1);
                unpack2(tB, c0, c1);
                aggA += fmaxf(a0 + bjA, 0.f) * r0 + fmaxf(a1 + bjA, 0.f) * r1;
                aggB += fmaxf(c0 + bjB, 0.f) * r0 + fmaxf(c1 + bjB, 0.f) * r1;
            }
            red_s[g * NH + lane]      = aggA;
            red_s[g * NH + lane + 32] = aggB;
        }
        __syncthreads();

        if (tid < NH)
            agg_s[tid] = red_s[tid] + red_s[NH + tid] + red_s[2 * NH + tid] + red_s[3 * NH + tid];
        __syncthreads();

        // Node MLP: aug = [x (4), agg (64)]
        if (tid < NH) {
            const float* w = out1_w + tid * (ND + NH);
            float acc = out1_b[tid];
#pragma unroll
            for (int d = 0; d < ND; d++) acc += w[d] * x_s[d];
#pragma unroll
            for (int k = 0; k < NH; k++) acc += w[ND + k] * agg_s[k];
            m1_s[tid] = fmaxf(acc, 0.f);
        }
        __syncthreads();
        if (tid < NH) {
            const float* w = out2_w + tid * NH;
            float acc = out2_b[tid];
#pragma unroll
            for (int k = 0; k < NH; k++) acc += w[k] * m1_s[k];
            m2_s[tid] = fmaxf(acc, 0.f);
        }
        __syncthreads();
        if (tid < ND) {
            const float* w = out3_w + tid * NH;
            float acc = out3_b[tid];
#pragma unroll
            for (int k = 0; k < NH; k++) acc += w[k] * m2_s[k];
            out[(((size_t)b * NN + n) * TO + t) * ND + tid] = x_s[tid] + acc;
        }
    }
}

// ---------------------------------------------------------------------------
extern "C" void kernel_launch(void* const* d_in, const int* in_sizes, int n_in,
                              void* d_out, int out_size) {
    const float* inputs   = (const float*)d_in[0];
    const float* rel_type = (const float*)d_in[1];
    // d_in[2] rel_rec, d_in[3] rel_send: one-hot by construction; indices analytic
    const float* fc1_w    = (const float*)d_in[4];
    const float* fc1_b    = (const float*)d_in[5];
    const float* fc2_w    = (const float*)d_in[6];
    const float* fc2_b    = (const float*)d_in[7];
    const float* out1_w   = (const float*)d_in[8];
    const float* out1_b   = (const float*)d_in[9];
    const float* out2_w   = (const float*)d_in[10];
    const float* out2_b   = (const float*)d_in[11];
    const float* out3_w   = (const float*)d_in[12];
    const float* out3_b   = (const float*)d_in[13];
    float* out = (float*)d_out;

    const int n_embed = NB * TO * NN * NH;
    k_node_embed<<<(n_embed + 255) / 256, 256>>>(inputs, fc1_w, fc1_b, fc2_w);

    k_edge<<<EDGE_GRID, 256>>>(inputs, rel_type, fc2_b,
                               out1_w, out1_b, out2_w, out2_b,
                               out3_w, out3_b, out);
}

// round 6
// speedup vs baseline: 1.3010x; 1.1756x over previous
#include <cuda_runtime.h>
#include <cuda_bf16.h>
#include <cstdint>

#define NB 8
#define NN 64
#define NT 50
#define TO 49
#define ND 4
#define NH 64
#define EPN 63
#define NNODES (NB * TO * NN)     // 25088
#define GRID 296
#define EREL (NN * EPN)           // 4032

typedef unsigned int u32;

__device__ float g_u[NNODES * NH];
__device__ float g_v[NNODES * NH];

// ---- smem layout (bytes) --------------------------------------------------
#define OFF_A_HI 0                // 64 rows x 128B bf16 = 8192 (swizzled)
#define OFF_A_LO 8192             // 8192
#define OFF_RED  16384            // 64 x 72 floats = 18432
#define OFF_U    34816            // 64 f
#define OFF_RT   35072            // 64 f
#define OFF_AGG  35328            // 64 f
#define OFF_M1   35584            // 64 f
#define OFF_M2   35840            // 64 f
#define OFF_X    36096            // 4 f
#define SMEM_SZ  36112
#define RED_S    72               // floats per red row

#define SWZ(o) ((o) ^ (((o) >> 3) & 0x70))

static __device__ __forceinline__ u32 smem_u32(const void* p) {
    u32 a;
    asm("{ .reg .u64 t; cvta.to.shared.u64 t, %1; cvt.u32.u64 %0, t; }" : "=r"(a) : "l"(p));
    return a;
}

static __device__ __forceinline__ void ldm4(u32* r, u32 addr) {
    asm volatile("ldmatrix.sync.aligned.m8n8.x4.shared.b16 {%0,%1,%2,%3}, [%4];"
        : "=r"(r[0]), "=r"(r[1]), "=r"(r[2]), "=r"(r[3]) : "r"(addr));
}

static __device__ __forceinline__ void mma_bf16(float* c, const u32* a, u32 b0, u32 b1) {
    asm volatile("mma.sync.aligned.m16n8k16.row.col.f32.bf16.bf16.f32 "
        "{%0,%1,%2,%3}, {%4,%5,%6,%7}, {%8,%9}, {%0,%1,%2,%3};"
        : "+f"(c[0]), "+f"(c[1]), "+f"(c[2]), "+f"(c[3])
        : "r"(a[0]), "r"(a[1]), "r"(a[2]), "r"(a[3]), "r"(b0), "r"(b1));
}

static __device__ __forceinline__ u32 bfx2(float x, float y) {
    __nv_bfloat162 p = __floats2bfloat162_rn(x, y);
    return *(u32*)&p;
}

// ---------------------------------------------------------------------------
// Kernel 1: per-node fc1 factorization (fp32).
__global__ void k_node_embed(const float* __restrict__ inputs,
                             const float* __restrict__ fc1_w,
                             const float* __restrict__ fc1_b) {
    int gid = blockIdx.x * blockDim.x + threadIdx.x;
    if (gid >= NNODES * NH) return;
    int h    = gid & 63;
    int node = gid >> 6;
    int n    = node & 63;
    int bt   = node >> 6;
    int t    = bt % TO;
    int b    = bt / TO;

    const float* x = inputs + (((size_t)b * NN + n) * NT + t) * ND;
    const float* w = fc1_w + NH * 2 * ND + h * 2 * ND;
    float u = fc1_b[NH + h];
    float v = 0.f;
#pragma unroll
    for (int d = 0; d < ND; d++) {
        u += w[d] * x[d];
        v += w[ND + d] * x[d];
    }
    g_u[gid] = u;
    g_v[gid] = v;
}

// ---------------------------------------------------------------------------
// Kernel 2: persistent mma.sync edge-GEMM (bf16x3) + fused epilogue/node MLP.
// One node per iteration: D[64 slots, 64 out] = h[64,64] @ W2t. 8 warps:
// warp = mh (row-half, wid>>2) x nq (16-col quarter, wid&3).
__global__ void __launch_bounds__(256, 2)
k_edge_mma(const float* __restrict__ inputs,
           const float* __restrict__ rel_type,
           const float* __restrict__ fc2_w, const float* __restrict__ fc2_b,
           const float* __restrict__ out1_w, const float* __restrict__ out1_b,
           const float* __restrict__ out2_w, const float* __restrict__ out2_b,
           const float* __restrict__ out3_w, const float* __restrict__ out3_b,
           float* __restrict__ out) {
    __shared__ char smem[SMEM_SZ];
    const u32 smb = smem_u32(smem);
    const int tid  = threadIdx.x;
    const int lane = tid & 31;
    const int wid  = tid >> 5;
    const int mh   = wid >> 2;       // row half (0/1): rows mh*32..+32
    const int nq   = wid & 3;        // col quarter: cols nq*16..+16

    float* u_s   = (float*)(smem + OFF_U);
    float* rt_s  = (float*)(smem + OFF_RT);
    float* agg_s = (float*)(smem + OFF_AGG);
    float* m1_s  = (float*)(smem + OFF_M1);
    float* m2_s  = (float*)(smem + OFF_M2);
    float* x_s   = (float*)(smem + OFF_X);
    float* red   = (float*)(smem + OFF_RED);

    // --- W2 B-fragments into registers, once. B[k][col] = fc2_w[1][col][k].
    u32 bhi[4][2][2], blo[4][2][2];
    float bj0[2], bj1[2];
#pragma unroll
    for (int kt = 0; kt < 4; kt++)
#pragma unroll
        for (int nt = 0; nt < 2; nt++) {
            int k0  = kt * 16 + (lane & 3) * 2;
            int col = nq * 16 + nt * 8 + (lane >> 2);
            const float* wc = fc2_w + NH * NH + col * NH;
            float w00 = wc[k0],     w01 = wc[k0 + 1];
            float w10 = wc[k0 + 8], w11 = wc[k0 + 9];
            float h00 = __bfloat162float(__float2bfloat16_rn(w00));
            float h01 = __bfloat162float(__float2bfloat16_rn(w01));
            float h10 = __bfloat162float(__float2bfloat16_rn(w10));
            float h11 = __bfloat162float(__float2bfloat16_rn(w11));
            bhi[kt][nt][0] = bfx2(h00, h01);
            bhi[kt][nt][1] = bfx2(h10, h11);
            blo[kt][nt][0] = bfx2(w00 - h00, w01 - h01);
            blo[kt][nt][1] = bfx2(w10 - h10, w11 - h11);
        }
#pragma unroll
    for (int nt = 0; nt < 2; nt++) {
        int col = nq * 16 + nt * 8 + (lane & 3) * 2;
        bj0[nt] = fc2_b[NH + col];
        bj1[nt] = fc2_b[NH + col + 1];
    }

    for (int node = blockIdx.x; node < NNODES; node += GRID) {
        const int n  = node & 63;
        const int bt = node >> 6;
        const int t  = bt % TO;
        const int b  = bt / TO;

        __syncthreads();   // prev iteration fully retired

        if (tid < 64) {
            u_s[tid] = g_u[(size_t)node * NH + tid];
        } else if (tid < 128) {
            int s = tid - 64;
            rt_s[s] = (s < EPN)
                ? rel_type[((size_t)b * EREL + n * EPN + s) * 2 + 1] : 0.f;
        } else if (tid < 132) {
            int d = tid - 128;
            x_s[d] = inputs[(((size_t)b * NN + n) * NT + t) * ND + d];
        }
        __syncthreads();

        // --- stage A: h[row=slot][k] as bf16 hi/lo, SW128-swizzled.
        {
            const int row  = tid >> 2;
            const int kseg = (tid & 3) * 16;
            const int send = (row >= EPN) ? n : (row + (row >= n ? 1 : 0));
            const float4* v4 = (const float4*)(g_v + ((size_t)(bt * NN) + send) * NH + kseg);
            uint4 hi[2], lo[2];
#pragma unroll
            for (int c = 0; c < 2; c++) {
                float4 va = v4[c * 2], vb = v4[c * 2 + 1];
                float h0 = fmaxf(u_s[kseg + c * 8 + 0] + va.x, 0.f);
                float h1 = fmaxf(u_s[kseg + c * 8 + 1] + va.y, 0.f);
                float h2 = fmaxf(u_s[kseg + c * 8 + 2] + va.z, 0.f);
                float h3 = fmaxf(u_s[kseg + c * 8 + 3] + va.w, 0.f);
                float h4 = fmaxf(u_s[kseg + c * 8 + 4] + vb.x, 0.f);
                float h5 = fmaxf(u_s[kseg + c * 8 + 5] + vb.y, 0.f);
                float h6 = fmaxf(u_s[kseg + c * 8 + 6] + vb.z, 0.f);
                float h7 = fmaxf(u_s[kseg + c * 8 + 7] + vb.w, 0.f);
                float p0 = __bfloat162float(__float2bfloat16_rn(h0));
                float p1 = __bfloat162float(__float2bfloat16_rn(h1));
                float p2 = __bfloat162float(__float2bfloat16_rn(h2));
                float p3 = __bfloat162float(__float2bfloat16_rn(h3));
                float p4 = __bfloat162float(__float2bfloat16_rn(h4));
                float p5 = __bfloat162float(__float2bfloat16_rn(h5));
                float p6 = __bfloat162float(__float2bfloat16_rn(h6));
                float p7 = __bfloat162float(__float2bfloat16_rn(h7));
                hi[c] = make_uint4(bfx2(p0, p1), bfx2(p2, p3), bfx2(p4, p5), bfx2(p6, p7));
                lo[c] = make_uint4(bfx2(h0 - p0, h1 - p1), bfx2(h2 - p2, h3 - p3),
                                   bfx2(h4 - p4, h5 - p5), bfx2(h6 - p6, h7 - p7));
            }
#pragma unroll
            for (int c = 0; c < 2; c++) {
                u32 off = row * 128 + kseg * 2 + c * 16;
                u32 sw  = SWZ(off);
                *(uint4*)(smem + OFF_A_HI + sw) = hi[c];
                *(uint4*)(smem + OFF_A_LO + sw) = lo[c];
            }
        }
        __syncthreads();

        // --- MMA: 2 m-tiles x 2 n-tiles x 4 k-steps x 3 passes.
        float acc[2][2][4];
#pragma unroll
        for (int mt = 0; mt < 2; mt++)
#pragma unroll
            for (int nt = 0; nt < 2; nt++)
#pragma unroll
                for (int q = 0; q < 4; q++) acc[mt][nt][q] = 0.f;

#pragma unroll
        for (int kt = 0; kt < 4; kt++) {
            u32 ah0[4], ah1[4], al0[4], al1[4];
            const int rrow  = (lane & 15);
            const int kbyte = kt * 32 + (lane >> 4) * 16;
            u32 o0 = (mh * 32 + rrow) * 128 + kbyte;
            u32 o1 = (mh * 32 + 16 + rrow) * 128 + kbyte;
            ldm4(ah0, smb + OFF_A_HI + SWZ(o0));
            ldm4(ah1, smb + OFF_A_HI + SWZ(o1));
            ldm4(al0, smb + OFF_A_LO + SWZ(o0));
            ldm4(al1, smb + OFF_A_LO + SWZ(o1));
#pragma unroll
            for (int nt = 0; nt < 2; nt++) {
                mma_bf16(acc[0][nt], ah0, bhi[kt][nt][0], bhi[kt][nt][1]);
                mma_bf16(acc[1][nt], ah1, bhi[kt][nt][0], bhi[kt][nt][1]);
                mma_bf16(acc[0][nt], al0, bhi[kt][nt][0], bhi[kt][nt][1]);
                mma_bf16(acc[1][nt], al1, bhi[kt][nt][0], bhi[kt][nt][1]);
                mma_bf16(acc[0][nt], ah0, blo[kt][nt][0], blo[kt][nt][1]);
                mma_bf16(acc[1][nt], ah1, blo[kt][nt][0], blo[kt][nt][1]);
            }
        }

        // --- epilogue: relu(+bias)*rt -> red[row][col]
#pragma unroll
        for (int mt = 0; mt < 2; mt++)
#pragma unroll
            for (int nt = 0; nt < 2; nt++) {
                int row = mh * 32 + mt * 16 + (lane >> 2);
                int col = nq * 16 + nt * 8 + (lane & 3) * 2;
                float r0 = rt_s[row], r8 = rt_s[row + 8];
                float2 v0, v8;
                v0.x = fmaxf(acc[mt][nt][0] + bj0[nt], 0.f) * r0;
                v0.y = fmaxf(acc[mt][nt][1] + bj1[nt], 0.f) * r0;
                v8.x = fmaxf(acc[mt][nt][2] + bj0[nt], 0.f) * r8;
                v8.y = fmaxf(acc[mt][nt][3] + bj1[nt], 0.f) * r8;
                *(float2*)(red + (size_t)row * RED_S + col)       = v0;
                *(float2*)(red + (size_t)(row + 8) * RED_S + col) = v8;
            }
        __syncthreads();

        // --- reduce over 64 edge slots -> agg[64]
        if (tid < 128) {
            int j = tid & 63, half = tid >> 6;
            const float* rr = red + (size_t)(half * 32) * RED_S + j;
            float a = 0.f;
#pragma unroll
            for (int s = 0; s < 32; s++) a += rr[(size_t)s * RED_S];
            if (half == 0) agg_s[j] = a;
            else m1_s[j] = a;     // temp stash for the other half
        }
        __syncthreads();
        if (tid < 64) agg_s[tid] += m1_s[tid];
        __syncthreads();

        // --- node MLP
        if (tid < 64) {
            const float* w = out1_w + tid * (ND + NH);
            float acc1 = out1_b[tid];
#pragma unroll
            for (int d = 0; d < ND; d++) acc1 += w[d] * x_s[d];
#pragma unroll
            for (int k = 0; k < NH; k++) acc1 += w[ND + k] * agg_s[k];
            m1_s[tid] = fmaxf(acc1, 0.f);
        }
        __syncthreads();
        if (tid < 64) {
            const float* w = out2_w + tid * NH;
            float acc2 = out2_b[tid];
#pragma unroll
            for (int k = 0; k < NH; k++) acc2 += w[k] * m1_s[k];
            m2_s[tid] = fmaxf(acc2, 0.f);
        }
        __syncthreads();
        if (tid < ND) {
            const float* w = out3_w + tid * NH;
            float acc3 = out3_b[tid];
#pragma unroll
            for (int k = 0; k < NH; k++) acc3 += w[k] * m2_s[k];
            out[(((size_t)b * NN + n) * TO + t) * ND + tid] = x_s[tid] + acc3;
        }
    }
}

// ---------------------------------------------------------------------------
extern "C" void kernel_launch(void* const* d_in, const int* in_sizes, int n_in,
                              void* d_out, int out_size) {
    const float* inputs   = (const float*)d_in[0];
    const float* rel_type = (const float*)d_in[1];
    const float* fc1_w    = (const float*)d_in[4];
    const float* fc1_b    = (const float*)d_in[5];
    const float* fc2_w    = (const float*)d_in[6];
    const float* fc2_b    = (const float*)d_in[7];
    const float* out1_w   = (const float*)d_in[8];
    const float* out1_b   = (const float*)d_in[9];
    const float* out2_w   = (const float*)d_in[10];
    const float* out2_b   = (const float*)d_in[11];
    const float* out3_w   = (const float*)d_in[12];
    const float* out3_b   = (const float*)d_in[13];
    float* out = (float*)d_out;

    const int n_embed = NNODES * NH;
    k_node_embed<<<(n_embed + 255) / 256, 256>>>(inputs, fc1_w, fc1_b);

    k_edge_mma<<<GRID, 256>>>(inputs, rel_type, fc2_w, fc2_b,
                              out1_w, out1_b, out2_w, out2_b,
                              out3_w, out3_b, out);
}

// round 7
// speedup vs baseline: 1.3581x; 1.0439x over previous
#include <cuda_runtime.h>
#include <cuda_bf16.h>
#include <cstdint>

#define NB 8
#define NN 64
#define NT 50
#define TO 49
#define ND 4
#define NH 64
#define EPN 63
#define NNODES (NB * TO * NN)     // 25088
#define NTILES (NNODES / 2)       // 12544 (tile = 2 adjacent recv nodes)
#define GRID 296
#define EREL (NN * EPN)           // 4032

typedef unsigned int u32;

__device__ float g_u[NNODES * NH];
__device__ float g_v[NNODES * NH];

// ---- smem layout (bytes) --------------------------------------------------
#define OFF_A_HI 0                // 128 rows x 128B = 16384 (SW128)
#define OFF_A_LO 16384            // 16384
#define OFF_RT   32768            // 128 f
#define OFF_AGG  33280            // 128 f
#define OFF_M1   33792            // 128 f
#define OFF_M2   34304            // 128 f
#define OFF_X    34816            // 8 f
#define SMEM_SZ  34848

#define SWZ(o) ((o) ^ (((o) >> 3) & 0x70))

static __device__ __forceinline__ u32 smem_u32(const void* p) {
    u32 a;
    asm("{ .reg .u64 t; cvta.to.shared.u64 t, %1; cvt.u32.u64 %0, t; }" : "=r"(a) : "l"(p));
    return a;
}
static __device__ __forceinline__ void ldm4(u32* r, u32 addr) {
    asm volatile("ldmatrix.sync.aligned.m8n8.x4.shared.b16 {%0,%1,%2,%3}, [%4];"
        : "=r"(r[0]), "=r"(r[1]), "=r"(r[2]), "=r"(r[3]) : "r"(addr));
}
static __device__ __forceinline__ void mma_bf16(float* c, const u32* a, u32 b0, u32 b1) {
    asm volatile("mma.sync.aligned.m16n8k16.row.col.f32.bf16.bf16.f32 "
        "{%0,%1,%2,%3}, {%4,%5,%6,%7}, {%8,%9}, {%0,%1,%2,%3};"
        : "+f"(c[0]), "+f"(c[1]), "+f"(c[2]), "+f"(c[3])
        : "r"(a[0]), "r"(a[1]), "r"(a[2]), "r"(a[3]), "r"(b0), "r"(b1));
}
static __device__ __forceinline__ u32 bfx2(float x, float y) {
    __nv_bfloat162 p = __floats2bfloat162_rn(x, y);
    return *(u32*)&p;
}

// ---------------------------------------------------------------------------
// Kernel 1: per-node fc1 factorization (fp32).
__global__ void k_node_embed(const float* __restrict__ inputs,
                             const float* __restrict__ fc1_w,
                             const float* __restrict__ fc1_b) {
    int gid = blockIdx.x * blockDim.x + threadIdx.x;
    if (gid >= NNODES * NH) return;
    int h    = gid & 63;
    int node = gid >> 6;
    int n    = node & 63;
    int bt   = node >> 6;
    int t    = bt % TO;
    int b    = bt / TO;

    const float* x = inputs + (((size_t)b * NN + n) * NT + t) * ND;
    const float* w = fc1_w + NH * 2 * ND + h * 2 * ND;
    float u = fc1_b[NH + h];
    float v = 0.f;
#pragma unroll
    for (int d = 0; d < ND; d++) {
        u += w[d] * x[d];
        v += w[ND + d] * x[d];
    }
    g_u[gid] = u;
    g_v[gid] = v;
}

// ---------------------------------------------------------------------------
// Kernel 2: persistent mma.sync edge-GEMM (bf16x3), 2 nodes/iteration.
// M=128 (2 nodes x 64 slots), N=64, K=64. 8 warps: mh = wid>>2 (node-local
// row half? NO: mh = node index 0/1, covering ALL 64 rows of that node),
// nq = wid&3 (16-col quarter). Edge-reduction done in-register + shfl.
__global__ void __launch_bounds__(256, 2)
k_edge_mma(const float* __restrict__ inputs,
           const float* __restrict__ rel_type,
           const float* __restrict__ fc2_w, const float* __restrict__ fc2_b,
           const float* __restrict__ out1_w, const float* __restrict__ out1_b,
           const float* __restrict__ out2_w, const float* __restrict__ out2_b,
           const float* __restrict__ out3_w, const float* __restrict__ out3_b,
           float* __restrict__ out) {
    __shared__ __align__(1024) char smem[SMEM_SZ];
    const u32 smb = smem_u32(smem);
    const int tid  = threadIdx.x;
    const int lane = tid & 31;
    const int wid  = tid >> 5;
    const int mh   = wid >> 2;       // node within tile (0/1): rows mh*64..+64
    const int nq   = wid & 3;        // col quarter: cols nq*16..+16

    float* rt_s  = (float*)(smem + OFF_RT);    // [2][64]
    float* agg_s = (float*)(smem + OFF_AGG);   // [2][64]
    float* m1_s  = (float*)(smem + OFF_M1);
    float* m2_s  = (float*)(smem + OFF_M2);
    float* x_s   = (float*)(smem + OFF_X);     // [2][4]

    // --- W2 B-fragments into registers, once. B[k][col] = fc2_w[1][col][k].
    u32 bhi[4][2][2], blo[4][2][2];
    float bj0[2], bj1[2];
#pragma unroll
    for (int kt = 0; kt < 4; kt++)
#pragma unroll
        for (int nt = 0; nt < 2; nt++) {
            int k0  = kt * 16 + (lane & 3) * 2;
            int col = nq * 16 + nt * 8 + (lane >> 2);
            const float* wc = fc2_w + NH * NH + col * NH;
            float w00 = wc[k0],     w01 = wc[k0 + 1];
            float w10 = wc[k0 + 8], w11 = wc[k0 + 9];
            float h00 = __bfloat162float(__float2bfloat16_rn(w00));
            float h01 = __bfloat162float(__float2bfloat16_rn(w01));
            float h10 = __bfloat162float(__float2bfloat16_rn(w10));
            float h11 = __bfloat162float(__float2bfloat16_rn(w11));
            bhi[kt][nt][0] = bfx2(h00, h01);
            bhi[kt][nt][1] = bfx2(h10, h11);
            blo[kt][nt][0] = bfx2(w00 - h00, w01 - h01);
            blo[kt][nt][1] = bfx2(w10 - h10, w11 - h11);
        }
#pragma unroll
    for (int nt = 0; nt < 2; nt++) {
        int col = nq * 16 + nt * 8 + (lane & 3) * 2;
        bj0[nt] = fc2_b[NH + col];
        bj1[nt] = fc2_b[NH + col + 1];
    }

    for (int tile = blockIdx.x; tile < NTILES; tile += GRID) {
        const int node0 = tile * 2;
        const int bt = node0 >> 6;
        const int t  = bt % TO;
        const int b  = bt / TO;
        const int n0 = node0 & 63;

        __syncthreads();   // prev iteration's smem consumers retired

        // rt + x (concurrent with staging; consumed only after the next sync)
        if (tid < 128) {
            int nl = tid >> 6, s = tid & 63;
            rt_s[tid] = (s < EPN)
                ? rel_type[((size_t)b * EREL + (n0 + nl) * EPN + s) * 2 + 1] : 0.f;
        } else if (tid < 136) {
            int q = tid - 128;
            x_s[q] = inputs[(((size_t)b * NN + (n0 + (q >> 2))) * NT + t) * ND + (q & 3)];
        }

        // --- stage A: row = tid>>1 (0..127), k-half = (tid&1)*32. u via LDG.
        {
            const int row = tid >> 1;
            const int kh  = (tid & 1) * 32;
            const int nl  = row >> 6;
            const int s   = row & 63;
            const int nr  = n0 + nl;
            const int send = (s >= EPN) ? nr : (s + (s >= nr ? 1 : 0));
            const float4* u4 = (const float4*)(g_u + ((size_t)(node0 + nl)) * NH + kh);
            const float4* v4 = (const float4*)(g_v + ((size_t)(bt * NN) + send) * NH + kh);
#pragma unroll
            for (int c = 0; c < 4; c++) {
                float4 ua = u4[c * 2], ub = u4[c * 2 + 1];
                float4 va = v4[c * 2], vb = v4[c * 2 + 1];
                float h0 = fmaxf(ua.x + va.x, 0.f), h1 = fmaxf(ua.y + va.y, 0.f);
                float h2 = fmaxf(ua.z + va.z, 0.f), h3 = fmaxf(ua.w + va.w, 0.f);
                float h4 = fmaxf(ub.x + vb.x, 0.f), h5 = fmaxf(ub.y + vb.y, 0.f);
                float h6 = fmaxf(ub.z + vb.z, 0.f), h7 = fmaxf(ub.w + vb.w, 0.f);
                float p0 = __bfloat162float(__float2bfloat16_rn(h0));
                float p1 = __bfloat162float(__float2bfloat16_rn(h1));
                float p2 = __bfloat162float(__float2bfloat16_rn(h2));
                float p3 = __bfloat162float(__float2bfloat16_rn(h3));
                float p4 = __bfloat162float(__float2bfloat16_rn(h4));
                float p5 = __bfloat162float(__float2bfloat16_rn(h5));
                float p6 = __bfloat162float(__float2bfloat16_rn(h6));
                float p7 = __bfloat162float(__float2bfloat16_rn(h7));
                uint4 hi = make_uint4(bfx2(p0, p1), bfx2(p2, p3), bfx2(p4, p5), bfx2(p6, p7));
                uint4 lo = make_uint4(bfx2(h0 - p0, h1 - p1), bfx2(h2 - p2, h3 - p3),
                                      bfx2(h4 - p4, h5 - p5), bfx2(h6 - p6, h7 - p7));
                u32 off = row * 128 + kh * 2 + c * 16;
                u32 sw  = SWZ(off);
                *(uint4*)(smem + OFF_A_HI + sw) = hi;
                *(uint4*)(smem + OFF_A_LO + sw) = lo;
            }
        }
        __syncthreads();

        // --- MMA: 4 mt row-tiles (covering node mh's 64 slots) x 2 nt x 4 kt x 3 passes
        float acc[4][2][4];
#pragma unroll
        for (int mt = 0; mt < 4; mt++)
#pragma unroll
            for (int nt = 0; nt < 2; nt++)
#pragma unroll
                for (int q = 0; q < 4; q++) acc[mt][nt][q] = 0.f;

#pragma unroll
        for (int kt = 0; kt < 4; kt++) {
            u32 ah[4][4], al[4][4];
            const int rrow  = (lane & 15);
            const int kbyte = kt * 32 + (lane >> 4) * 16;
#pragma unroll
            for (int mt = 0; mt < 4; mt++) {
                u32 o = (mh * 64 + mt * 16 + rrow) * 128 + kbyte;
                ldm4(ah[mt], smb + OFF_A_HI + SWZ(o));
                ldm4(al[mt], smb + OFF_A_LO + SWZ(o));
            }
#pragma unroll
            for (int nt = 0; nt < 2; nt++)
#pragma unroll
                for (int mt = 0; mt < 4; mt++) {
                    mma_bf16(acc[mt][nt], ah[mt], bhi[kt][nt][0], bhi[kt][nt][1]);
                    mma_bf16(acc[mt][nt], al[mt], bhi[kt][nt][0], bhi[kt][nt][1]);
                    mma_bf16(acc[mt][nt], ah[mt], blo[kt][nt][0], blo[kt][nt][1]);
                }
        }

        // --- epilogue + in-warp edge reduction (no smem matrix).
        float red4[4];
#pragma unroll
        for (int nt = 0; nt < 2; nt++) {
            float s0 = 0.f, s1 = 0.f;
#pragma unroll
            for (int mt = 0; mt < 4; mt++) {
                float r0 = rt_s[mh * 64 + mt * 16 + (lane >> 2)];
                float r8 = rt_s[mh * 64 + mt * 16 + (lane >> 2) + 8];
                s0 += fmaxf(acc[mt][nt][0] + bj0[nt], 0.f) * r0
                    + fmaxf(acc[mt][nt][2] + bj0[nt], 0.f) * r8;
                s1 += fmaxf(acc[mt][nt][1] + bj1[nt], 0.f) * r0
                    + fmaxf(acc[mt][nt][3] + bj1[nt], 0.f) * r8;
            }
            red4[nt * 2]     = s0;
            red4[nt * 2 + 1] = s1;
        }
#pragma unroll
        for (int off = 4; off < 32; off <<= 1)
#pragma unroll
            for (int i = 0; i < 4; i++)
                red4[i] += __shfl_xor_sync(0xffffffffu, red4[i], off);
        if (lane < 4) {
            int base = mh * 64 + nq * 16 + lane * 2;
            agg_s[base]     = red4[0];
            agg_s[base + 1] = red4[1];
            agg_s[base + 8] = red4[2];
            agg_s[base + 9] = red4[3];
        }
        __syncthreads();

        // --- node MLP for the 2 nodes
        if (tid < 128) {
            int nl = tid >> 6, o = tid & 63;
            const float* w = out1_w + o * (ND + NH);
            float a1 = out1_b[o];
#pragma unroll
            for (int d = 0; d < ND; d++) a1 += w[d] * x_s[nl * 4 + d];
#pragma unroll
            for (int k = 0; k < NH; k++) a1 += w[ND + k] * agg_s[nl * 64 + k];
            m1_s[tid] = fmaxf(a1, 0.f);
        }
        __syncthreads();
        if (tid < 128) {
            int nl = tid >> 6, o = tid & 63;
            const float* w = out2_w + o * NH;
            float a2 = out2_b[o];
#pragma unroll
            for (int k = 0; k < NH; k++) a2 += w[k] * m1_s[nl * 64 + k];
            m2_s[tid] = fmaxf(a2, 0.f);
        }
        __syncthreads();
        if (tid < 8) {
            int nl = tid >> 2, dd = tid & 3;
            const float* w = out3_w + dd * NH;
            float a3 = out3_b[dd];
#pragma unroll
            for (int k = 0; k < NH; k++) a3 += w[k] * m2_s[nl * 64 + k];
            out[(((size_t)b * NN + (n0 + nl)) * TO + t) * ND + dd] = x_s[nl * 4 + dd] + a3;
        }
    }
}

// ---------------------------------------------------------------------------
extern "C" void kernel_launch(void* const* d_in, const int* in_sizes, int n_in,
                              void* d_out, int out_size) {
    const float* inputs   = (const float*)d_in[0];
    const float* rel_type = (const float*)d_in[1];
    const float* fc1_w    = (const float*)d_in[4];
    const float* fc1_b    = (const float*)d_in[5];
    const float* fc2_w    = (const float*)d_in[6];
    const float* fc2_b    = (const float*)d_in[7];
    const float* out1_w   = (const float*)d_in[8];
    const float* out1_b   = (const float*)d_in[9];
    const float* out2_w   = (const float*)d_in[10];
    const float* out2_b   = (const float*)d_in[11];
    const float* out3_w   = (const float*)d_in[12];
    const float* out3_b   = (const float*)d_in[13];
    float* out = (float*)d_out;

    const int n_embed = NNODES * NH;
    k_node_embed<<<(n_embed + 255) / 256, 256>>>(inputs, fc1_w, fc1_b);

    k_edge_mma<<<GRID, 256>>>(inputs, rel_type, fc2_w, fc2_b,
                              out1_w, out1_b, out2_w, out2_b,
                              out3_w, out3_b, out);
}

// round 8
// speedup vs baseline: 3.3442x; 2.4625x over previous
#include <cuda_runtime.h>
#include <cuda_bf16.h>
#include <cstdint>

#define NB 8
#define NN 64
#define NT 50
#define TO 49
#define ND 4
#define NH 64
#define EPN 63
#define NNODES (NB * TO * NN)     // 25088
#define NTILES (NNODES / 2)       // 12544 (tile = 2 adjacent recv nodes)
#define GRID 296
#define EREL (NN * EPN)           // 4032

typedef unsigned int u32;

__device__ float g_u[NNODES * NH];
__device__ float g_v[NNODES * NH];
__device__ float g_w1t[(ND + NH) * NH];   // out1_w^T: [k][o]
__device__ float g_w2nt[NH * NH];         // out2_w^T: [k][o]

// ---- smem layout (bytes) --------------------------------------------------
#define OFF_A_HI 0                // 128 rows x 128B = 16384 (SW128)
#define OFF_A_LO 16384            // 16384
#define OFF_RT   32768            // 128 f
#define OFF_AGG  33280            // 128 f
#define OFF_M1   33792            // 128 f
#define OFF_M2   34304            // 128 f
#define OFF_X    34816            // 8 f
#define SMEM_SZ  34848

#define SWZ(o) ((o) ^ (((o) >> 3) & 0x70))

static __device__ __forceinline__ u32 smem_u32(const void* p) {
    u32 a;
    asm("{ .reg .u64 t; cvta.to.shared.u64 t, %1; cvt.u32.u64 %0, t; }" : "=r"(a) : "l"(p));
    return a;
}
static __device__ __forceinline__ void ldm4(u32* r, u32 addr) {
    asm volatile("ldmatrix.sync.aligned.m8n8.x4.shared.b16 {%0,%1,%2,%3}, [%4];"
        : "=r"(r[0]), "=r"(r[1]), "=r"(r[2]), "=r"(r[3]) : "r"(addr));
}
static __device__ __forceinline__ void mma_bf16(float* c, const u32* a, u32 b0, u32 b1) {
    asm volatile("mma.sync.aligned.m16n8k16.row.col.f32.bf16.bf16.f32 "
        "{%0,%1,%2,%3}, {%4,%5,%6,%7}, {%8,%9}, {%0,%1,%2,%3};"
        : "+f"(c[0]), "+f"(c[1]), "+f"(c[2]), "+f"(c[3])
        : "r"(a[0]), "r"(a[1]), "r"(a[2]), "r"(a[3]), "r"(b0), "r"(b1));
}
static __device__ __forceinline__ u32 bfx2(float x, float y) {
    __nv_bfloat162 p = __floats2bfloat162_rn(x, y);
    return *(u32*)&p;
}

// ---------------------------------------------------------------------------
// Kernel 1: per-node fc1 factorization (fp32) + node-MLP weight transposes.
__global__ void k_node_embed(const float* __restrict__ inputs,
                             const float* __restrict__ fc1_w,
                             const float* __restrict__ fc1_b,
                             const float* __restrict__ out1_w,
                             const float* __restrict__ out2_w) {
    int gid = blockIdx.x * blockDim.x + threadIdx.x;
    if (gid < (ND + NH) * NH) {
        int k = gid >> 6, o = gid & 63;
        g_w1t[k * NH + o] = out1_w[o * (ND + NH) + k];
    }
    if (gid < NH * NH) {
        int k = gid >> 6, o = gid & 63;
        g_w2nt[k * NH + o] = out2_w[o * NH + k];
    }
    if (gid >= NNODES * NH) return;
    int h    = gid & 63;
    int node = gid >> 6;
    int n    = node & 63;
    int bt   = node >> 6;
    int t    = bt % TO;
    int b    = bt / TO;

    const float* x = inputs + (((size_t)b * NN + n) * NT + t) * ND;
    const float* w = fc1_w + NH * 2 * ND + h * 2 * ND;
    float u = fc1_b[NH + h];
    float v = 0.f;
#pragma unroll
    for (int d = 0; d < ND; d++) {
        u += w[d] * x[d];
        v += w[ND + d] * x[d];
    }
    g_u[gid] = u;
    g_v[gid] = v;
}

// ---------------------------------------------------------------------------
// Kernel 2: persistent mma.sync edge-GEMM (bf16x3), 2 nodes/iteration.
// M=128 (2 nodes x 64 slots), N=64, K=64. 8 warps: mh = node in tile (0/1),
// nq = 16-col quarter. Edge reduction in-register + shfl. Node MLP reads
// pre-transposed weights (coalesced).
__global__ void __launch_bounds__(256, 2)
k_edge_mma(const float* __restrict__ inputs,
           const float* __restrict__ rel_type,
           const float* __restrict__ fc2_w, const float* __restrict__ fc2_b,
           const float* __restrict__ out1_b,
           const float* __restrict__ out2_b,
           const float* __restrict__ out3_w, const float* __restrict__ out3_b,
           float* __restrict__ out) {
    __shared__ __align__(1024) char smem[SMEM_SZ];
    const u32 smb = smem_u32(smem);
    const int tid  = threadIdx.x;
    const int lane = tid & 31;
    const int wid  = tid >> 5;
    const int mh   = wid >> 2;       // node within tile (0/1)
    const int nq   = wid & 3;        // col quarter

    float* rt_s  = (float*)(smem + OFF_RT);    // [2][64]
    float* agg_s = (float*)(smem + OFF_AGG);   // [2][64]
    float* m1_s  = (float*)(smem + OFF_M1);
    float* m2_s  = (float*)(smem + OFF_M2);
    float* x_s   = (float*)(smem + OFF_X);     // [2][4]

    // --- W2 B-fragments into registers, once. B[k][col] = fc2_w[1][col][k].
    u32 bhi[4][2][2], blo[4][2][2];
    float bj0[2], bj1[2];
#pragma unroll
    for (int kt = 0; kt < 4; kt++)
#pragma unroll
        for (int nt = 0; nt < 2; nt++) {
            int k0  = kt * 16 + (lane & 3) * 2;
            int col = nq * 16 + nt * 8 + (lane >> 2);
            const float* wc = fc2_w + NH * NH + col * NH;
            float w00 = wc[k0],     w01 = wc[k0 + 1];
            float w10 = wc[k0 + 8], w11 = wc[k0 + 9];
            float h00 = __bfloat162float(__float2bfloat16_rn(w00));
            float h01 = __bfloat162float(__float2bfloat16_rn(w01));
            float h10 = __bfloat162float(__float2bfloat16_rn(w10));
            float h11 = __bfloat162float(__float2bfloat16_rn(w11));
            bhi[kt][nt][0] = bfx2(h00, h01);
            bhi[kt][nt][1] = bfx2(h10, h11);
            blo[kt][nt][0] = bfx2(w00 - h00, w01 - h01);
            blo[kt][nt][1] = bfx2(w10 - h10, w11 - h11);
        }
#pragma unroll
    for (int nt = 0; nt < 2; nt++) {
        int col = nq * 16 + nt * 8 + (lane & 3) * 2;
        bj0[nt] = fc2_b[NH + col];
        bj1[nt] = fc2_b[NH + col + 1];
    }

    for (int tile = blockIdx.x; tile < NTILES; tile += GRID) {
        const int node0 = tile * 2;
        const int bt = node0 >> 6;
        const int t  = bt % TO;
        const int b  = bt / TO;
        const int n0 = node0 & 63;

        __syncthreads();   // prev iteration's smem consumers retired

        if (tid < 128) {
            int nl = tid >> 6, s = tid & 63;
            rt_s[tid] = (s < EPN)
                ? rel_type[((size_t)b * EREL + (n0 + nl) * EPN + s) * 2 + 1] : 0.f;
        } else if (tid < 136) {
            int q = tid - 128;
            x_s[q] = inputs[(((size_t)b * NN + (n0 + (q >> 2))) * NT + t) * ND + (q & 3)];
        }

        // --- stage A: row = tid>>1 (0..127), k-half = (tid&1)*32.
        {
            const int row = tid >> 1;
            const int kh  = (tid & 1) * 32;
            const int nl  = row >> 6;
            const int s   = row & 63;
            const int nr  = n0 + nl;
            const int send = (s >= EPN) ? nr : (s + (s >= nr ? 1 : 0));
            const float4* u4 = (const float4*)(g_u + ((size_t)(node0 + nl)) * NH + kh);
            const float4* v4 = (const float4*)(g_v + ((size_t)(bt * NN) + send) * NH + kh);
#pragma unroll
            for (int c = 0; c < 4; c++) {
                float4 ua = u4[c * 2], ub = u4[c * 2 + 1];
                float4 va = v4[c * 2], vb = v4[c * 2 + 1];
                float h0 = fmaxf(ua.x + va.x, 0.f), h1 = fmaxf(ua.y + va.y, 0.f);
                float h2 = fmaxf(ua.z + va.z, 0.f), h3 = fmaxf(ua.w + va.w, 0.f);
                float h4 = fmaxf(ub.x + vb.x, 0.f), h5 = fmaxf(ub.y + vb.y, 0.f);
                float h6 = fmaxf(ub.z + vb.z, 0.f), h7 = fmaxf(ub.w + vb.w, 0.f);
                float p0 = __bfloat162float(__float2bfloat16_rn(h0));
                float p1 = __bfloat162float(__float2bfloat16_rn(h1));
                float p2 = __bfloat162float(__float2bfloat16_rn(h2));
                float p3 = __bfloat162float(__float2bfloat16_rn(h3));
                float p4 = __bfloat162float(__float2bfloat16_rn(h4));
                float p5 = __bfloat162float(__float2bfloat16_rn(h5));
                float p6 = __bfloat162float(__float2bfloat16_rn(h6));
                float p7 = __bfloat162float(__float2bfloat16_rn(h7));
                uint4 hi = make_uint4(bfx2(p0, p1), bfx2(p2, p3), bfx2(p4, p5), bfx2(p6, p7));
                uint4 lo = make_uint4(bfx2(h0 - p0, h1 - p1), bfx2(h2 - p2, h3 - p3),
                                      bfx2(h4 - p4, h5 - p5), bfx2(h6 - p6, h7 - p7));
                u32 off = row * 128 + kh * 2 + c * 16;
                u32 sw  = SWZ(off);
                *(uint4*)(smem + OFF_A_HI + sw) = hi;
                *(uint4*)(smem + OFF_A_LO + sw) = lo;
            }
        }
        __syncthreads();

        // --- MMA: 4 mt row-tiles (node mh's 64 slots) x 2 nt x 4 kt x 3 passes
        float acc[4][2][4];
#pragma unroll
        for (int mt = 0; mt < 4; mt++)
#pragma unroll
            for (int nt = 0; nt < 2; nt++)
#pragma unroll
                for (int q = 0; q < 4; q++) acc[mt][nt][q] = 0.f;

#pragma unroll
        for (int kt = 0; kt < 4; kt++) {
            u32 ah[4][4], al[4][4];
            const int rrow  = (lane & 15);
            const int kbyte = kt * 32 + (lane >> 4) * 16;
#pragma unroll
            for (int mt = 0; mt < 4; mt++) {
                u32 o = (mh * 64 + mt * 16 + rrow) * 128 + kbyte;
                ldm4(ah[mt], smb + OFF_A_HI + SWZ(o));
                ldm4(al[mt], smb + OFF_A_LO + SWZ(o));
            }
#pragma unroll
            for (int nt = 0; nt < 2; nt++)
#pragma unroll
                for (int mt = 0; mt < 4; mt++) {
                    mma_bf16(acc[mt][nt], ah[mt], bhi[kt][nt][0], bhi[kt][nt][1]);
                    mma_bf16(acc[mt][nt], al[mt], bhi[kt][nt][0], bhi[kt][nt][1]);
                    mma_bf16(acc[mt][nt], ah[mt], blo[kt][nt][0], blo[kt][nt][1]);
                }
        }

        // --- epilogue + in-warp edge reduction
        float red4[4];
#pragma unroll
        for (int nt = 0; nt < 2; nt++) {
            float s0 = 0.f, s1 = 0.f;
#pragma unroll
            for (int mt = 0; mt < 4; mt++) {
                float r0 = rt_s[mh * 64 + mt * 16 + (lane >> 2)];
                float r8 = rt_s[mh * 64 + mt * 16 + (lane >> 2) + 8];
                s0 += fmaxf(acc[mt][nt][0] + bj0[nt], 0.f) * r0
                    + fmaxf(acc[mt][nt][2] + bj0[nt], 0.f) * r8;
                s1 += fmaxf(acc[mt][nt][1] + bj1[nt], 0.f) * r0
                    + fmaxf(acc[mt][nt][3] + bj1[nt], 0.f) * r8;
            }
            red4[nt * 2]     = s0;
            red4[nt * 2 + 1] = s1;
        }
#pragma unroll
        for (int off = 4; off < 32; off <<= 1)
#pragma unroll
            for (int i = 0; i < 4; i++)
                red4[i] += __shfl_xor_sync(0xffffffffu, red4[i], off);
        if (lane < 4) {
            int base = mh * 64 + nq * 16 + lane * 2;
            agg_s[base]     = red4[0];
            agg_s[base + 1] = red4[1];
            agg_s[base + 8] = red4[2];
            agg_s[base + 9] = red4[3];
        }
        __syncthreads();

        // --- node MLP (transposed weights: coalesced LDG, broadcast LDS)
        if (tid < 128) {
            int nl = tid >> 6, o = tid & 63;
            float a1 = out1_b[o];
#pragma unroll
            for (int d = 0; d < ND; d++) a1 += g_w1t[d * NH + o] * x_s[nl * 4 + d];
#pragma unroll
            for (int k = 0; k < NH; k++) a1 += g_w1t[(ND + k) * NH + o] * agg_s[nl * 64 + k];
            m1_s[tid] = fmaxf(a1, 0.f);
        }
        __syncthreads();
        if (tid < 128) {
            int nl = tid >> 6, o = tid & 63;
            float a2 = out2_b[o];
#pragma unroll
            for (int k = 0; k < NH; k++) a2 += g_w2nt[k * NH + o] * m1_s[nl * 64 + k];
            m2_s[tid] = fmaxf(a2, 0.f);
        }
        __syncthreads();
        if (tid < 8) {
            int nl = tid >> 2, dd = tid & 3;
            const float* w = out3_w + dd * NH;
            float a3 = out3_b[dd];
#pragma unroll
            for (int k = 0; k < NH; k++) a3 += w[k] * m2_s[nl * 64 + k];
            out[(((size_t)b * NN + (n0 + nl)) * TO + t) * ND + dd] = x_s[nl * 4 + dd] + a3;
        }
    }
}

// ---------------------------------------------------------------------------
extern "C" void kernel_launch(void* const* d_in, const int* in_sizes, int n_in,
                              void* d_out, int out_size) {
    const float* inputs   = (const float*)d_in[0];
    const float* rel_type = (const float*)d_in[1];
    const float* fc1_w    = (const float*)d_in[4];
    const float* fc1_b    = (const float*)d_in[5];
    const float* fc2_w    = (const float*)d_in[6];
    const float* fc2_b    = (const float*)d_in[7];
    const float* out1_w   = (const float*)d_in[8];
    const float* out1_b   = (const float*)d_in[9];
    const float* out2_w   = (const float*)d_in[10];
    const float* out2_b   = (const float*)d_in[11];
    const float* out3_w   = (const float*)d_in[12];
    const float* out3_b   = (const float*)d_in[13];
    float* out = (float*)d_out;

    const int n_embed = NNODES * NH;
    k_node_embed<<<(n_embed + 255) / 256, 256>>>(inputs, fc1_w, fc1_b, out1_w, out2_w);

    k_edge_mma<<<GRID, 256>>>(inputs, rel_type, fc2_w, fc2_b,
                              out1_b, out2_b, out3_w, out3_b, out);
}

// round 9
// speedup vs baseline: 3.7212x; 1.1127x over previous
#include <cuda_runtime.h>
#include <cuda_fp16.h>
#include <cstdint>

#define NB 8
#define NN 64
#define NT 50
#define TO 49
#define ND 4
#define NH 64
#define EPN 63
#define NNODES (NB * TO * NN)     // 25088
#define NTILES (NNODES / 2)       // 12544 (tile = 2 adjacent recv nodes)
#define GRID 296
#define EREL (NN * EPN)           // 4032

typedef unsigned int u32;

__device__ float g_u[NNODES * NH];
__device__ float g_v[NNODES * NH];
__device__ float g_w1t[(ND + NH) * NH];   // out1_w^T: [k][o]
__device__ float g_w2nt[NH * NH];         // out2_w^T: [k][o]

// ---- smem layout (bytes) --------------------------------------------------
#define OFF_A    0                // 128 rows x 128B fp16 = 16384 (SW128)
#define OFF_RT   16384            // 128 f
#define OFF_AGG  16896            // 128 f
#define OFF_M1   17408            // 128 f
#define OFF_M2   17920            // 128 f
#define OFF_X    18432            // 8 f
#define SMEM_SZ  18464

#define SWZ(o) ((o) ^ (((o) >> 3) & 0x70))

static __device__ __forceinline__ u32 smem_u32(const void* p) {
    u32 a;
    asm("{ .reg .u64 t; cvta.to.shared.u64 t, %1; cvt.u32.u64 %0, t; }" : "=r"(a) : "l"(p));
    return a;
}
static __device__ __forceinline__ void ldm4(u32* r, u32 addr) {
    asm volatile("ldmatrix.sync.aligned.m8n8.x4.shared.b16 {%0,%1,%2,%3}, [%4];"
        : "=r"(r[0]), "=r"(r[1]), "=r"(r[2]), "=r"(r[3]) : "r"(addr));
}
static __device__ __forceinline__ void mma_f16(float* c, const u32* a, u32 b0, u32 b1) {
    asm volatile("mma.sync.aligned.m16n8k16.row.col.f32.f16.f16.f32 "
        "{%0,%1,%2,%3}, {%4,%5,%6,%7}, {%8,%9}, {%0,%1,%2,%3};"
        : "+f"(c[0]), "+f"(c[1]), "+f"(c[2]), "+f"(c[3])
        : "r"(a[0]), "r"(a[1]), "r"(a[2]), "r"(a[3]), "r"(b0), "r"(b1));
}
static __device__ __forceinline__ u32 hfx2(float x, float y) {
    __half2 p = __floats2half2_rn(x, y);
    return *(u32*)&p;
}

// ---------------------------------------------------------------------------
// Kernel 1: per-node fc1 factorization (fp32) + node-MLP weight transposes.
__global__ void k_node_embed(const float* __restrict__ inputs,
                             const float* __restrict__ fc1_w,
                             const float* __restrict__ fc1_b,
                             const float* __restrict__ out1_w,
                             const float* __restrict__ out2_w) {
    int gid = blockIdx.x * blockDim.x + threadIdx.x;
    if (gid < (ND + NH) * NH) {
        int k = gid >> 6, o = gid & 63;
        g_w1t[k * NH + o] = out1_w[o * (ND + NH) + k];
    }
    if (gid < NH * NH) {
        int k = gid >> 6, o = gid & 63;
        g_w2nt[k * NH + o] = out2_w[o * NH + k];
    }
    if (gid >= NNODES * NH) return;
    int h    = gid & 63;
    int node = gid >> 6;
    int n    = node & 63;
    int bt   = node >> 6;
    int t    = bt % TO;
    int b    = bt / TO;

    const float* x = inputs + (((size_t)b * NN + n) * NT + t) * ND;
    const float* w = fc1_w + NH * 2 * ND + h * 2 * ND;
    float u = fc1_b[NH + h];
    float v = 0.f;
#pragma unroll
    for (int d = 0; d < ND; d++) {
        u += w[d] * x[d];
        v += w[ND + d] * x[d];
    }
    g_u[gid] = u;
    g_v[gid] = v;
}

// ---------------------------------------------------------------------------
// Kernel 2: persistent mma.sync edge-GEMM, fp16 2-term (A single fp16,
// B = W2 split hi+lo in registers). 2 nodes/iteration, M=128, N=64, K=64.
// 8 warps: mh = node in tile (0/1), nq = 16-col quarter. In-register
// edge reduction via shfl; node MLP on pre-transposed weights.
__global__ void __launch_bounds__(256, 2)
k_edge_mma(const float* __restrict__ inputs,
           const float* __restrict__ rel_type,
           const float* __restrict__ fc2_w, const float* __restrict__ fc2_b,
           const float* __restrict__ out1_b,
           const float* __restrict__ out2_b,
           const float* __restrict__ out3_w, const float* __restrict__ out3_b,
           float* __restrict__ out) {
    __shared__ __align__(1024) char smem[SMEM_SZ];
    const u32 smb = smem_u32(smem);
    const int tid  = threadIdx.x;
    const int lane = tid & 31;
    const int wid  = tid >> 5;
    const int mh   = wid >> 2;       // node within tile (0/1)
    const int nq   = wid & 3;        // col quarter

    float* rt_s  = (float*)(smem + OFF_RT);    // [2][64]
    float* agg_s = (float*)(smem + OFF_AGG);   // [2][64]
    float* m1_s  = (float*)(smem + OFF_M1);
    float* m2_s  = (float*)(smem + OFF_M2);
    float* x_s   = (float*)(smem + OFF_X);     // [2][4]

    // --- W2 B-fragments (fp16 hi + residual lo) into registers, once.
    u32 bhi[4][2][2], blo[4][2][2];
    float bj0[2], bj1[2];
#pragma unroll
    for (int kt = 0; kt < 4; kt++)
#pragma unroll
        for (int nt = 0; nt < 2; nt++) {
            int k0  = kt * 16 + (lane & 3) * 2;
            int col = nq * 16 + nt * 8 + (lane >> 2);
            const float* wc = fc2_w + NH * NH + col * NH;
            float w00 = wc[k0],     w01 = wc[k0 + 1];
            float w10 = wc[k0 + 8], w11 = wc[k0 + 9];
            float h00 = __half2float(__float2half_rn(w00));
            float h01 = __half2float(__float2half_rn(w01));
            float h10 = __half2float(__float2half_rn(w10));
            float h11 = __half2float(__float2half_rn(w11));
            bhi[kt][nt][0] = hfx2(h00, h01);
            bhi[kt][nt][1] = hfx2(h10, h11);
            blo[kt][nt][0] = hfx2(w00 - h00, w01 - h01);
            blo[kt][nt][1] = hfx2(w10 - h10, w11 - h11);
        }
#pragma unroll
    for (int nt = 0; nt < 2; nt++) {
        int col = nq * 16 + nt * 8 + (lane & 3) * 2;
        bj0[nt] = fc2_b[NH + col];
        bj1[nt] = fc2_b[NH + col + 1];
    }

    for (int tile = blockIdx.x; tile < NTILES; tile += GRID) {
        const int node0 = tile * 2;
        const int bt = node0 >> 6;
        const int t  = bt % TO;
        const int b  = bt / TO;
        const int n0 = node0 & 63;

        __syncthreads();   // prev iteration's smem consumers retired

        if (tid < 128) {
            int nl = tid >> 6, s = tid & 63;
            rt_s[tid] = (s < EPN)
                ? rel_type[((size_t)b * EREL + (n0 + nl) * EPN + s) * 2 + 1] : 0.f;
        } else if (tid < 136) {
            int q = tid - 128;
            x_s[q] = inputs[(((size_t)b * NN + (n0 + (q >> 2))) * NT + t) * ND + (q & 3)];
        }

        // --- stage A: row = tid>>1 (0..127), k-half = (tid&1)*32. fp16 single.
        {
            const int row = tid >> 1;
            const int kh  = (tid & 1) * 32;
            const int nl  = row >> 6;
            const int s   = row & 63;
            const int nr  = n0 + nl;
            const int send = (s >= EPN) ? nr : (s + (s >= nr ? 1 : 0));
            const float4* u4 = (const float4*)(g_u + ((size_t)(node0 + nl)) * NH + kh);
            const float4* v4 = (const float4*)(g_v + ((size_t)(bt * NN) + send) * NH + kh);
#pragma unroll
            for (int c = 0; c < 4; c++) {
                float4 ua = u4[c * 2], ub = u4[c * 2 + 1];
                float4 va = v4[c * 2], vb = v4[c * 2 + 1];
                uint4 hv;
                hv.x = hfx2(fmaxf(ua.x + va.x, 0.f), fmaxf(ua.y + va.y, 0.f));
                hv.y = hfx2(fmaxf(ua.z + va.z, 0.f), fmaxf(ua.w + va.w, 0.f));
                hv.z = hfx2(fmaxf(ub.x + vb.x, 0.f), fmaxf(ub.y + vb.y, 0.f));
                hv.w = hfx2(fmaxf(ub.z + vb.z, 0.f), fmaxf(ub.w + vb.w, 0.f));
                u32 off = row * 128 + kh * 2 + c * 16;
                *(uint4*)(smem + OFF_A + SWZ(off)) = hv;
            }
        }
        __syncthreads();

        // --- MMA: 4 mt row-tiles (node mh's 64 slots) x 2 nt x 4 kt x 2 passes
        float acc[4][2][4];
#pragma unroll
        for (int mt = 0; mt < 4; mt++)
#pragma unroll
            for (int nt = 0; nt < 2; nt++)
#pragma unroll
                for (int q = 0; q < 4; q++) acc[mt][nt][q] = 0.f;

#pragma unroll
        for (int kt = 0; kt < 4; kt++) {
            u32 ah[4][4];
            const int rrow  = (lane & 15);
            const int kbyte = kt * 32 + (lane >> 4) * 16;
#pragma unroll
            for (int mt = 0; mt < 4; mt++) {
                u32 o = (mh * 64 + mt * 16 + rrow) * 128 + kbyte;
                ldm4(ah[mt], smb + OFF_A + SWZ(o));
            }
#pragma unroll
            for (int nt = 0; nt < 2; nt++)
#pragma unroll
                for (int mt = 0; mt < 4; mt++) {
                    mma_f16(acc[mt][nt], ah[mt], bhi[kt][nt][0], bhi[kt][nt][1]);
                    mma_f16(acc[mt][nt], ah[mt], blo[kt][nt][0], blo[kt][nt][1]);
                }
        }

        // --- epilogue + in-warp edge reduction
        float red4[4];
#pragma unroll
        for (int nt = 0; nt < 2; nt++) {
            float s0 = 0.f, s1 = 0.f;
#pragma unroll
            for (int mt = 0; mt < 4; mt++) {
                float r0 = rt_s[mh * 64 + mt * 16 + (lane >> 2)];
                float r8 = rt_s[mh * 64 + mt * 16 + (lane >> 2) + 8];
                s0 += fmaxf(acc[mt][nt][0] + bj0[nt], 0.f) * r0
                    + fmaxf(acc[mt][nt][2] + bj0[nt], 0.f) * r8;
                s1 += fmaxf(acc[mt][nt][1] + bj1[nt], 0.f) * r0
                    + fmaxf(acc[mt][nt][3] + bj1[nt], 0.f) * r8;
            }
            red4[nt * 2]     = s0;
            red4[nt * 2 + 1] = s1;
        }
#pragma unroll
        for (int off = 4; off < 32; off <<= 1)
#pragma unroll
            for (int i = 0; i < 4; i++)
                red4[i] += __shfl_xor_sync(0xffffffffu, red4[i], off);
        if (lane < 4) {
            int base = mh * 64 + nq * 16 + lane * 2;
            agg_s[base]     = red4[0];
            agg_s[base + 1] = red4[1];
            agg_s[base + 8] = red4[2];
            agg_s[base + 9] = red4[3];
        }
        __syncthreads();

        // --- node MLP (transposed weights: coalesced LDG, broadcast LDS)
        if (tid < 128) {
            int nl = tid >> 6, o = tid & 63;
            float a1 = out1_b[o];
#pragma unroll
            for (int d = 0; d < ND; d++) a1 += g_w1t[d * NH + o] * x_s[nl * 4 + d];
#pragma unroll
            for (int k = 0; k < NH; k++) a1 += g_w1t[(ND + k) * NH + o] * agg_s[nl * 64 + k];
            m1_s[tid] = fmaxf(a1, 0.f);
        }
        __syncthreads();
        if (tid < 128) {
            int nl = tid >> 6, o = tid & 63;
            float a2 = out2_b[o];
#pragma unroll
            for (int k = 0; k < NH; k++) a2 += g_w2nt[k * NH + o] * m1_s[nl * 64 + k];
            m2_s[tid] = fmaxf(a2, 0.f);
        }
        __syncthreads();
        if (tid < 8) {
            int nl = tid >> 2, dd = tid & 3;
            const float* w = out3_w + dd * NH;
            float a3 = out3_b[dd];
#pragma unroll
            for (int k = 0; k < NH; k++) a3 += w[k] * m2_s[nl * 64 + k];
            out[(((size_t)b * NN + (n0 + nl)) * TO + t) * ND + dd] = x_s[nl * 4 + dd] + a3;
        }
    }
}

// ---------------------------------------------------------------------------
extern "C" void kernel_launch(void* const* d_in, const int* in_sizes, int n_in,
                              void* d_out, int out_size) {
    const float* inputs   = (const float*)d_in[0];
    const float* rel_type = (const float*)d_in[1];
    const float* fc1_w    = (const float*)d_in[4];
    const float* fc1_b    = (const float*)d_in[5];
    const float* fc2_w    = (const float*)d_in[6];
    const float* fc2_b    = (const float*)d_in[7];
    const float* out1_w   = (const float*)d_in[8];
    const float* out1_b   = (const float*)d_in[9];
    const float* out2_w   = (const float*)d_in[10];
    const float* out2_b   = (const float*)d_in[11];
    const float* out3_w   = (const float*)d_in[12];
    const float* out3_b   = (const float*)d_in[13];
    float* out = (float*)d_out;

    const int n_embed = NNODES * NH;
    k_node_embed<<<(n_embed + 255) / 256, 256>>>(inputs, fc1_w, fc1_b, out1_w, out2_w);

    k_edge_mma<<<GRID, 256>>>(inputs, rel_type, fc2_w, fc2_b,
                              out1_b, out2_b, out3_w, out3_b, out);
}

// round 10
// speedup vs baseline: 4.2902x; 1.1529x over previous
#include <cuda_runtime.h>
#include <cuda_fp16.h>
#include <cstdint>

#define NB 8
#define NN 64
#define NT 50
#define TO 49
#define ND 4
#define NH 64
#define EPN 63
#define NNODES (NB * TO * NN)     // 25088
#define NTILES (NNODES / 2)       // 12544
#define GRID 296
#define EREL (NN * EPN)           // 4032
#define NBT (NB * TO)             // 392

typedef unsigned int u32;

__device__ float g_u[NNODES * NH];
__device__ float g_v[NNODES * NH];
__device__ float g_agg[NNODES * NH];      // edge-aggregated messages
__device__ float g_w1t[(ND + NH) * NH];   // out1_w^T: [k][o]
__device__ float g_w2nt[NH * NH];         // out2_w^T: [k][o]

// ---- edge-kernel smem layout (bytes) ---------------------------------------
#define OFF_A    0                // 128 rows x 128B fp16 = 16384 (SW128)
#define OFF_RT   16384            // 128 f
#define SMEM_SZ  16896

#define SWZ(o) ((o) ^ (((o) >> 3) & 0x70))

static __device__ __forceinline__ u32 smem_u32(const void* p) {
    u32 a;
    asm("{ .reg .u64 t; cvta.to.shared.u64 t, %1; cvt.u32.u64 %0, t; }" : "=r"(a) : "l"(p));
    return a;
}
static __device__ __forceinline__ void ldm4(u32* r, u32 addr) {
    asm volatile("ldmatrix.sync.aligned.m8n8.x4.shared.b16 {%0,%1,%2,%3}, [%4];"
        : "=r"(r[0]), "=r"(r[1]), "=r"(r[2]), "=r"(r[3]) : "r"(addr));
}
static __device__ __forceinline__ void mma_f16(float* c, const u32* a, u32 b0, u32 b1) {
    asm volatile("mma.sync.aligned.m16n8k16.row.col.f32.f16.f16.f32 "
        "{%0,%1,%2,%3}, {%4,%5,%6,%7}, {%8,%9}, {%0,%1,%2,%3};"
        : "+f"(c[0]), "+f"(c[1]), "+f"(c[2]), "+f"(c[3])
        : "r"(a[0]), "r"(a[1]), "r"(a[2]), "r"(a[3]), "r"(b0), "r"(b1));
}
static __device__ __forceinline__ u32 hfx2(float x, float y) {
    __half2 p = __floats2half2_rn(x, y);
    return *(u32*)&p;
}

// ---------------------------------------------------------------------------
// Kernel 1: per-node fc1 factorization (fp32) + node-MLP weight transposes.
__global__ void k_node_embed(const float* __restrict__ inputs,
                             const float* __restrict__ fc1_w,
                             const float* __restrict__ fc1_b,
                             const float* __restrict__ out1_w,
                             const float* __restrict__ out2_w) {
    int gid = blockIdx.x * blockDim.x + threadIdx.x;
    if (gid < (ND + NH) * NH) {
        int k = gid >> 6, o = gid & 63;
        g_w1t[k * NH + o] = out1_w[o * (ND + NH) + k];
    }
    if (gid < NH * NH) {
        int k = gid >> 6, o = gid & 63;
        g_w2nt[k * NH + o] = out2_w[o * NH + k];
    }
    if (gid >= NNODES * NH) return;
    int h    = gid & 63;
    int node = gid >> 6;
    int n    = node & 63;
    int bt   = node >> 6;
    int t    = bt % TO;
    int b    = bt / TO;

    const float* x = inputs + (((size_t)b * NN + n) * NT + t) * ND;
    const float* w = fc1_w + NH * 2 * ND + h * 2 * ND;
    float u = fc1_b[NH + h];
    float v = 0.f;
#pragma unroll
    for (int d = 0; d < ND; d++) {
        u += w[d] * x[d];
        v += w[ND + d] * x[d];
    }
    g_u[gid] = u;
    g_v[gid] = v;
}

// ---------------------------------------------------------------------------
// Kernel 2: persistent mma.sync edge-GEMM (fp16 A single, W2 hi+lo in regs).
// 2 nodes/iteration; writes agg straight to g_agg (node MLP moved out).
__global__ void __launch_bounds__(256, 2)
k_edge_mma(const float* __restrict__ rel_type,
           const float* __restrict__ fc2_w, const float* __restrict__ fc2_b) {
    __shared__ __align__(1024) char smem[SMEM_SZ];
    const u32 smb = smem_u32(smem);
    const int tid  = threadIdx.x;
    const int lane = tid & 31;
    const int wid  = tid >> 5;
    const int mh   = wid >> 2;       // node within tile (0/1)
    const int nq   = wid & 3;        // col quarter

    float* rt_s = (float*)(smem + OFF_RT);    // [2][64]

    // --- W2 B-fragments (fp16 hi + residual lo) into registers, once.
    u32 bhi[4][2][2], blo[4][2][2];
    float bj0[2], bj1[2];
#pragma unroll
    for (int kt = 0; kt < 4; kt++)
#pragma unroll
        for (int nt = 0; nt < 2; nt++) {
            int k0  = kt * 16 + (lane & 3) * 2;
            int col = nq * 16 + nt * 8 + (lane >> 2);
            const float* wc = fc2_w + NH * NH + col * NH;
            float w00 = wc[k0],     w01 = wc[k0 + 1];
            float w10 = wc[k0 + 8], w11 = wc[k0 + 9];
            float h00 = __half2float(__float2half_rn(w00));
            float h01 = __half2float(__float2half_rn(w01));
            float h10 = __half2float(__float2half_rn(w10));
            float h11 = __half2float(__float2half_rn(w11));
            bhi[kt][nt][0] = hfx2(h00, h01);
            bhi[kt][nt][1] = hfx2(h10, h11);
            blo[kt][nt][0] = hfx2(w00 - h00, w01 - h01);
            blo[kt][nt][1] = hfx2(w10 - h10, w11 - h11);
        }
#pragma unroll
    for (int nt = 0; nt < 2; nt++) {
        int col = nq * 16 + nt * 8 + (lane & 3) * 2;
        bj0[nt] = fc2_b[NH + col];
        bj1[nt] = fc2_b[NH + col + 1];
    }

    for (int tile = blockIdx.x; tile < NTILES; tile += GRID) {
        const int node0 = tile * 2;
        const int bt = node0 >> 6;
        const int b  = bt / TO;
        const int n0 = node0 & 63;

        __syncthreads();   // prev iteration's rt/A consumers retired

        if (tid < 128) {
            int nl = tid >> 6, s = tid & 63;
            rt_s[tid] = (s < EPN)
                ? rel_type[((size_t)b * EREL + (n0 + nl) * EPN + s) * 2 + 1] : 0.f;
        }

        // --- stage A: row = tid>>1 (0..127), k-half = (tid&1)*32. fp16.
        {
            const int row = tid >> 1;
            const int kh  = (tid & 1) * 32;
            const int nl  = row >> 6;
            const int s   = row & 63;
            const int nr  = n0 + nl;
            const int send = (s >= EPN) ? nr : (s + (s >= nr ? 1 : 0));
            const float4* u4 = (const float4*)(g_u + ((size_t)(node0 + nl)) * NH + kh);
            const float4* v4 = (const float4*)(g_v + ((size_t)(bt * NN) + send) * NH + kh);
#pragma unroll
            for (int c = 0; c < 4; c++) {
                float4 ua = u4[c * 2], ub = u4[c * 2 + 1];
                float4 va = v4[c * 2], vb = v4[c * 2 + 1];
                uint4 hv;
                hv.x = hfx2(fmaxf(ua.x + va.x, 0.f), fmaxf(ua.y + va.y, 0.f));
                hv.y = hfx2(fmaxf(ua.z + va.z, 0.f), fmaxf(ua.w + va.w, 0.f));
                hv.z = hfx2(fmaxf(ub.x + vb.x, 0.f), fmaxf(ub.y + vb.y, 0.f));
                hv.w = hfx2(fmaxf(ub.z + vb.z, 0.f), fmaxf(ub.w + vb.w, 0.f));
                u32 off = row * 128 + kh * 2 + c * 16;
                *(uint4*)(smem + OFF_A + SWZ(off)) = hv;
            }
        }
        __syncthreads();

        // --- MMA: 4 mt row-tiles x 2 nt x 4 kt x 2 passes
        float acc[4][2][4];
#pragma unroll
        for (int mt = 0; mt < 4; mt++)
#pragma unroll
            for (int nt = 0; nt < 2; nt++)
#pragma unroll
                for (int q = 0; q < 4; q++) acc[mt][nt][q] = 0.f;

#pragma unroll
        for (int kt = 0; kt < 4; kt++) {
            u32 ah[4][4];
            const int rrow  = (lane & 15);
            const int kbyte = kt * 32 + (lane >> 4) * 16;
#pragma unroll
            for (int mt = 0; mt < 4; mt++) {
                u32 o = (mh * 64 + mt * 16 + rrow) * 128 + kbyte;
                ldm4(ah[mt], smb + OFF_A + SWZ(o));
            }
#pragma unroll
            for (int nt = 0; nt < 2; nt++)
#pragma unroll
                for (int mt = 0; mt < 4; mt++) {
                    mma_f16(acc[mt][nt], ah[mt], bhi[kt][nt][0], bhi[kt][nt][1]);
                    mma_f16(acc[mt][nt], ah[mt], blo[kt][nt][0], blo[kt][nt][1]);
                }
        }

        // --- epilogue + in-warp edge reduction -> g_agg
        float red4[4];
#pragma unroll
        for (int nt = 0; nt < 2; nt++) {
            float s0 = 0.f, s1 = 0.f;
#pragma unroll
            for (int mt = 0; mt < 4; mt++) {
                float r0 = rt_s[mh * 64 + mt * 16 + (lane >> 2)];
                float r8 = rt_s[mh * 64 + mt * 16 + (lane >> 2) + 8];
                s0 += fmaxf(acc[mt][nt][0] + bj0[nt], 0.f) * r0
                    + fmaxf(acc[mt][nt][2] + bj0[nt], 0.f) * r8;
                s1 += fmaxf(acc[mt][nt][1] + bj1[nt], 0.f) * r0
                    + fmaxf(acc[mt][nt][3] + bj1[nt], 0.f) * r8;
            }
            red4[nt * 2]     = s0;
            red4[nt * 2 + 1] = s1;
        }
#pragma unroll
        for (int off = 4; off < 32; off <<= 1)
#pragma unroll
            for (int i = 0; i < 4; i++)
                red4[i] += __shfl_xor_sync(0xffffffffu, red4[i], off);
        if (lane < 4) {
            float* ga = g_agg + (size_t)(node0 + mh) * NH + nq * 16 + lane * 2;
            *(float2*)(ga)     = make_float2(red4[0], red4[1]);
            *(float2*)(ga + 8) = make_float2(red4[2], red4[3]);
        }
    }
}

// ---------------------------------------------------------------------------
// Kernel 3: node MLP over all nodes. One (b,t) per block (392 blocks x 256).
// Warp w owns rows 8w..8w+8; lane owns outputs (lane, lane+32). k-loop is
// hoisted over the 8 rows so each weight load is amortized 8x.
__global__ void __launch_bounds__(256)
k_node_mlp(const float* __restrict__ inputs,
           const float* __restrict__ out1_b,
           const float* __restrict__ out2_b,
           const float* __restrict__ out3_w, const float* __restrict__ out3_b,
           float* __restrict__ out) {
    __shared__ float m1_s[64 * 65];
    __shared__ float m2_s[64 * 65];

    const int bt   = blockIdx.x;
    const int t    = bt % TO;
    const int b    = bt / TO;
    const int tid  = threadIdx.x;
    const int lane = tid & 31;
    const int wid  = tid >> 5;
    const int r0   = wid * 8;

    // ---- layer 1: [x(4), agg(64)] -> 64, relu
    {
        float a[8][2];
#pragma unroll
        for (int r = 0; r < 8; r++) {
            a[r][0] = out1_b[lane];
            a[r][1] = out1_b[lane + 32];
        }
#pragma unroll
        for (int d = 0; d < ND; d++) {
            float w0 = g_w1t[d * NH + lane];
            float w1 = g_w1t[d * NH + lane + 32];
#pragma unroll
            for (int r = 0; r < 8; r++) {
                float xv = inputs[(((size_t)b * NN + (r0 + r)) * NT + t) * ND + d];
                a[r][0] += w0 * xv;
                a[r][1] += w1 * xv;
            }
        }
        const float* ag = g_agg + ((size_t)bt * NN + r0) * NH;
        for (int k = 0; k < NH; k++) {
            float w0 = g_w1t[(ND + k) * NH + lane];
            float w1 = g_w1t[(ND + k) * NH + lane + 32];
#pragma unroll
            for (int r = 0; r < 8; r++) {
                float av = ag[r * NH + k];
                a[r][0] += w0 * av;
                a[r][1] += w1 * av;
            }
        }
#pragma unroll
        for (int r = 0; r < 8; r++) {
            m1_s[(r0 + r) * 65 + lane]      = fmaxf(a[r][0], 0.f);
            m1_s[(r0 + r) * 65 + lane + 32] = fmaxf(a[r][1], 0.f);
        }
    }
    __syncthreads();

    // ---- layer 2: 64 -> 64, relu
    {
        float a[8][2];
#pragma unroll
        for (int r = 0; r < 8; r++) {
            a[r][0] = out2_b[lane];
            a[r][1] = out2_b[lane + 32];
        }
        for (int k = 0; k < NH; k++) {
            float w0 = g_w2nt[k * NH + lane];
            float w1 = g_w2nt[k * NH + lane + 32];
#pragma unroll
            for (int r = 0; r < 8; r++) {
                float mv = m1_s[(r0 + r) * 65 + k];
                a[r][0] += w0 * mv;
                a[r][1] += w1 * mv;
            }
        }
#pragma unroll
        for (int r = 0; r < 8; r++) {
            m2_s[(r0 + r) * 65 + lane]      = fmaxf(a[r][0], 0.f);
            m2_s[(r0 + r) * 65 + lane + 32] = fmaxf(a[r][1], 0.f);
        }
    }
    __syncthreads();

    // ---- layer 3: 64 -> 4, + residual x, write output
    if (tid < 64) {
        const int n = tid;
        float a3[4];
#pragma unroll
        for (int d = 0; d < ND; d++) a3[d] = out3_b[d];
        for (int k = 0; k < NH; k++) {
            float mv = m2_s[n * 65 + k];
#pragma unroll
            for (int d = 0; d < ND; d++) a3[d] += out3_w[d * NH + k] * mv;
        }
        const float* x = inputs + (((size_t)b * NN + n) * NT + t) * ND;
        float* op = out + (((size_t)b * NN + n) * TO + t) * ND;
#pragma unroll
        for (int d = 0; d < ND; d++) op[d] = x[d] + a3[d];
    }
}

// ---------------------------------------------------------------------------
extern "C" void kernel_launch(void* const* d_in, const int* in_sizes, int n_in,
                              void* d_out, int out_size) {
    const float* inputs   = (const float*)d_in[0];
    const float* rel_type = (const float*)d_in[1];
    const float* fc1_w    = (const float*)d_in[4];
    const float* fc1_b    = (const float*)d_in[5];
    const float* fc2_w    = (const float*)d_in[6];
    const float* fc2_b    = (const float*)d_in[7];
    const float* out1_w   = (const float*)d_in[8];
    const float* out1_b   = (const float*)d_in[9];
    const float* out2_w   = (const float*)d_in[10];
    const float* out2_b   = (const float*)d_in[11];
    const float* out3_w   = (const float*)d_in[12];
    const float* out3_b   = (const float*)d_in[13];
    float* out = (float*)d_out;

    const int n_embed = NNODES * NH;
    k_node_embed<<<(n_embed + 255) / 256, 256>>>(inputs, fc1_w, fc1_b, out1_w, out2_w);

    k_edge_mma<<<GRID, 256>>>(rel_type, fc2_w, fc2_b);

    k_node_mlp<<<NBT, 256>>>(inputs, out1_b, out2_b, out3_w, out3_b, out);
}

// round 11
// speedup vs baseline: 7.3908x; 1.7227x over previous
#include <cuda_runtime.h>
#include <cuda_fp16.h>
#include <cstdint>

#define NB 8
#define NN 64
#define NT 50
#define TO 49
#define ND 4
#define NH 64
#define EPN 63
#define NNODES (NB * TO * NN)     // 25088
#define NTILES (NNODES / 2)       // 12544
#define GRID 296
#define EREL (NN * EPN)           // 4032
#define NBT (NB * TO)             // 392

typedef unsigned int u32;

__device__ __half g_uh[NNODES * NH];      // fp16 u' = W1r@x + b1
__device__ __half g_vh[NNODES * NH];      // fp16 v  = W1s@x
__device__ float g_agg[NNODES * NH];      // edge-aggregated messages
__device__ float g_w1t[(ND + NH) * NH];   // out1_w^T: [k][o]
__device__ float g_w2nt[NH * NH];         // out2_w^T: [k][o]

// ---- edge-kernel smem layout (bytes) ---------------------------------------
#define OFF_A    0                // 128 rows x 128B fp16 = 16384 (SW128)
#define OFF_RT   16384            // 128 f
#define SMEM_SZ  16896

#define SWZ(o) ((o) ^ (((o) >> 3) & 0x70))

static __device__ __forceinline__ u32 smem_u32(const void* p) {
    u32 a;
    asm("{ .reg .u64 t; cvta.to.shared.u64 t, %1; cvt.u32.u64 %0, t; }" : "=r"(a) : "l"(p));
    return a;
}
static __device__ __forceinline__ void ldm4(u32* r, u32 addr) {
    asm volatile("ldmatrix.sync.aligned.m8n8.x4.shared.b16 {%0,%1,%2,%3}, [%4];"
        : "=r"(r[0]), "=r"(r[1]), "=r"(r[2]), "=r"(r[3]) : "r"(addr));
}
static __device__ __forceinline__ void mma_f16(float* c, const u32* a, u32 b0, u32 b1) {
    asm volatile("mma.sync.aligned.m16n8k16.row.col.f32.f16.f16.f32 "
        "{%0,%1,%2,%3}, {%4,%5,%6,%7}, {%8,%9}, {%0,%1,%2,%3};"
        : "+f"(c[0]), "+f"(c[1]), "+f"(c[2]), "+f"(c[3])
        : "r"(a[0]), "r"(a[1]), "r"(a[2]), "r"(a[3]), "r"(b0), "r"(b1));
}
static __device__ __forceinline__ u32 hfx2(float x, float y) {
    __half2 p = __floats2half2_rn(x, y);
    return *(u32*)&p;
}
static __device__ __forceinline__ u32 hadd2_relu(u32 a, u32 b) {
    __half2 s = __hadd2(*(__half2*)&a, *(__half2*)&b);
    __half2 z = __float2half2_rn(0.f);
    __half2 r = __hmax2(s, z);
    return *(u32*)&r;
}

// ---------------------------------------------------------------------------
// Kernel 1: per-node fc1 factorization (fp32 math, fp16 store) + transposes.
__global__ void k_node_embed(const float* __restrict__ inputs,
                             const float* __restrict__ fc1_w,
                             const float* __restrict__ fc1_b,
                             const float* __restrict__ out1_w,
                             const float* __restrict__ out2_w) {
    int gid = blockIdx.x * blockDim.x + threadIdx.x;
    if (gid < (ND + NH) * NH) {
        int k = gid >> 6, o = gid & 63;
        g_w1t[k * NH + o] = out1_w[o * (ND + NH) + k];
    }
    if (gid < NH * NH) {
        int k = gid >> 6, o = gid & 63;
        g_w2nt[k * NH + o] = out2_w[o * NH + k];
    }
    if (gid >= NNODES * NH) return;
    int h    = gid & 63;
    int node = gid >> 6;
    int n    = node & 63;
    int bt   = node >> 6;
    int t    = bt % TO;
    int b    = bt / TO;

    const float* x = inputs + (((size_t)b * NN + n) * NT + t) * ND;
    const float* w = fc1_w + NH * 2 * ND + h * 2 * ND;
    float u = fc1_b[NH + h];
    float v = 0.f;
#pragma unroll
    for (int d = 0; d < ND; d++) {
        u += w[d] * x[d];
        v += w[ND + d] * x[d];
    }
    g_uh[gid] = __float2half_rn(u);
    g_vh[gid] = __float2half_rn(v);
}

// ---------------------------------------------------------------------------
// Kernel 2: persistent mma.sync edge-GEMM (fp16 A, W2 hi+lo in regs).
// 2 nodes/iteration; coalesced fp16 staging (half2 add+relu, no CVT);
// writes agg straight to g_agg.
__global__ void __launch_bounds__(256, 2)
k_edge_mma(const float* __restrict__ rel_type,
           const float* __restrict__ fc2_w, const float* __restrict__ fc2_b) {
    __shared__ __align__(1024) char smem[SMEM_SZ];
    const u32 smb = smem_u32(smem);
    const int tid  = threadIdx.x;
    const int lane = tid & 31;
    const int wid  = tid >> 5;
    const int mh   = wid >> 2;       // node within tile (0/1)
    const int nq   = wid & 3;        // col quarter

    float* rt_s = (float*)(smem + OFF_RT);    // [2][64]

    // --- W2 B-fragments (fp16 hi + residual lo) into registers, once.
    u32 bhi[4][2][2], blo[4][2][2];
    float bj0[2], bj1[2];
#pragma unroll
    for (int kt = 0; kt < 4; kt++)
#pragma unroll
        for (int nt = 0; nt < 2; nt++) {
            int k0  = kt * 16 + (lane & 3) * 2;
            int col = nq * 16 + nt * 8 + (lane >> 2);
            const float* wc = fc2_w + NH * NH + col * NH;
            float w00 = wc[k0],     w01 = wc[k0 + 1];
            float w10 = wc[k0 + 8], w11 = wc[k0 + 9];
            float h00 = __half2float(__float2half_rn(w00));
            float h01 = __half2float(__float2half_rn(w01));
            float h10 = __half2float(__float2half_rn(w10));
            float h11 = __half2float(__float2half_rn(w11));
            bhi[kt][nt][0] = hfx2(h00, h01);
            bhi[kt][nt][1] = hfx2(h10, h11);
            blo[kt][nt][0] = hfx2(w00 - h00, w01 - h01);
            blo[kt][nt][1] = hfx2(w10 - h10, w11 - h11);
        }
#pragma unroll
    for (int nt = 0; nt < 2; nt++) {
        int col = nq * 16 + nt * 8 + (lane & 3) * 2;
        bj0[nt] = fc2_b[NH + col];
        bj1[nt] = fc2_b[NH + col + 1];
    }

    for (int tile = blockIdx.x; tile < NTILES; tile += GRID) {
        const int node0 = tile * 2;
        const int bt = node0 >> 6;
        const int b  = bt / TO;
        const int n0 = node0 & 63;

        __syncthreads();   // prev iteration's rt/A consumers retired

        if (tid < 128) {
            int nl = tid >> 6, s = tid & 63;
            rt_s[tid] = (s < EPN)
                ? rel_type[((size_t)b * EREL + (n0 + nl) * EPN + s) * 2 + 1] : 0.f;
        }

        // --- stage A, coalesced: warp covers 2 full 128B rows per iteration.
        // lane -> (row = base + (lane>>4), seg = lane&15); 8B per lane.
        {
            const int seg = lane & 15;            // 8B chunk: halfs [seg*4, seg*4+4)
            const int rl  = lane >> 4;            // row within pair
#pragma unroll
            for (int it = 0; it < 8; it++) {
                const int r  = wid * 16 + it * 2 + rl;
                const int nl = r >> 6;
                const int s  = r & 63;
                const int nr = n0 + nl;
                const int send = (s >= EPN) ? nr : (s + (s >= nr ? 1 : 0));
                const uint2* uu = (const uint2*)(g_uh + ((size_t)(node0 + nl)) * NH) + seg;
                const uint2* vv = (const uint2*)(g_vh + ((size_t)(bt * NN) + send) * NH) + seg;
                uint2 ua = *uu;
                uint2 va = *vv;
                uint2 hv;
                hv.x = hadd2_relu(ua.x, va.x);
                hv.y = hadd2_relu(ua.y, va.y);
                u32 off = r * 128 + seg * 8;
                *(uint2*)(smem + OFF_A + SWZ(off)) = hv;
            }
        }
        __syncthreads();

        // --- MMA: 4 mt row-tiles x 2 nt x 4 kt x 2 passes
        float acc[4][2][4];
#pragma unroll
        for (int mt = 0; mt < 4; mt++)
#pragma unroll
            for (int nt = 0; nt < 2; nt++)
#pragma unroll
                for (int q = 0; q < 4; q++) acc[mt][nt][q] = 0.f;

#pragma unroll
        for (int kt = 0; kt < 4; kt++) {
            u32 ah[4][4];
            const int rrow  = (lane & 15);
            const int kbyte = kt * 32 + (lane >> 4) * 16;
#pragma unroll
            for (int mt = 0; mt < 4; mt++) {
                u32 o = (mh * 64 + mt * 16 + rrow) * 128 + kbyte;
                ldm4(ah[mt], smb + OFF_A + SWZ(o));
            }
#pragma unroll
            for (int nt = 0; nt < 2; nt++)
#pragma unroll
                for (int mt = 0; mt < 4; mt++) {
                    mma_f16(acc[mt][nt], ah[mt], bhi[kt][nt][0], bhi[kt][nt][1]);
                    mma_f16(acc[mt][nt], ah[mt], blo[kt][nt][0], blo[kt][nt][1]);
                }
        }

        // --- epilogue + in-warp edge reduction -> g_agg
        float red4[4];
#pragma unroll
        for (int nt = 0; nt < 2; nt++) {
            float s0 = 0.f, s1 = 0.f;
#pragma unroll
            for (int mt = 0; mt < 4; mt++) {
                float r0 = rt_s[mh * 64 + mt * 16 + (lane >> 2)];
                float r8 = rt_s[mh * 64 + mt * 16 + (lane >> 2) + 8];
                s0 += fmaxf(acc[mt][nt][0] + bj0[nt], 0.f) * r0
                    + fmaxf(acc[mt][nt][2] + bj0[nt], 0.f) * r8;
                s1 += fmaxf(acc[mt][nt][1] + bj1[nt], 0.f) * r0
                    + fmaxf(acc[mt][nt][3] + bj1[nt], 0.f) * r8;
            }
            red4[nt * 2]     = s0;
            red4[nt * 2 + 1] = s1;
        }
#pragma unroll
        for (int off = 4; off < 32; off <<= 1)
#pragma unroll
            for (int i = 0; i < 4; i++)
                red4[i] += __shfl_xor_sync(0xffffffffu, red4[i], off);
        if (lane < 4) {
            float* ga = g_agg + (size_t)(node0 + mh) * NH + nq * 16 + lane * 2;
            *(float2*)(ga)     = make_float2(red4[0], red4[1]);
            *(float2*)(ga + 8) = make_float2(red4[2], red4[3]);
        }
    }
}

// ---------------------------------------------------------------------------
// Kernel 3: node MLP over all nodes. One (b,t) per block (392 blocks x 256).
__global__ void __launch_bounds__(256)
k_node_mlp(const float* __restrict__ inputs,
           const float* __restrict__ out1_b,
           const float* __restrict__ out2_b,
           const float* __restrict__ out3_w, const float* __restrict__ out3_b,
           float* __restrict__ out) {
    __shared__ float m1_s[64 * 65];
    __shared__ float m2_s[64 * 65];

    const int bt   = blockIdx.x;
    const int t    = bt % TO;
    const int b    = bt / TO;
    const int tid  = threadIdx.x;
    const int lane = tid & 31;
    const int wid  = tid >> 5;
    const int r0   = wid * 8;

    // ---- layer 1: [x(4), agg(64)] -> 64, relu
    {
        float a[8][2];
#pragma unroll
        for (int r = 0; r < 8; r++) {
            a[r][0] = out1_b[lane];
            a[r][1] = out1_b[lane + 32];
        }
#pragma unroll
        for (int d = 0; d < ND; d++) {
            float w0 = g_w1t[d * NH + lane];
            float w1 = g_w1t[d * NH + lane + 32];
#pragma unroll
            for (int r = 0; r < 8; r++) {
                float xv = inputs[(((size_t)b * NN + (r0 + r)) * NT + t) * ND + d];
                a[r][0] += w0 * xv;
                a[r][1] += w1 * xv;
            }
        }
        const float* ag = g_agg + ((size_t)bt * NN + r0) * NH;
        for (int k = 0; k < NH; k++) {
            float w0 = g_w1t[(ND + k) * NH + lane];
            float w1 = g_w1t[(ND + k) * NH + lane + 32];
#pragma unroll
            for (int r = 0; r < 8; r++) {
                float av = ag[r * NH + k];
                a[r][0] += w0 * av;
                a[r][1] += w1 * av;
            }
        }
#pragma unroll
        for (int r = 0; r < 8; r++) {
            m1_s[(r0 + r) * 65 + lane]      = fmaxf(a[r][0], 0.f);
            m1_s[(r0 + r) * 65 + lane + 32] = fmaxf(a[r][1], 0.f);
        }
    }
    __syncthreads();

    // ---- layer 2: 64 -> 64, relu
    {
        float a[8][2];
#pragma unroll
        for (int r = 0; r < 8; r++) {
            a[r][0] = out2_b[lane];
            a[r][1] = out2_b[lane + 32];
        }
        for (int k = 0; k < NH; k++) {
            float w0 = g_w2nt[k * NH + lane];
            float w1 = g_w2nt[k * NH + lane + 32];
#pragma unroll
            for (int r = 0; r < 8; r++) {
                float mv = m1_s[(r0 + r) * 65 + k];
                a[r][0] += w0 * mv;
                a[r][1] += w1 * mv;
            }
        }
#pragma unroll
        for (int r = 0; r < 8; r++) {
            m2_s[(r0 + r) * 65 + lane]      = fmaxf(a[r][0], 0.f);
            m2_s[(r0 + r) * 65 + lane + 32] = fmaxf(a[r][1], 0.f);
        }
    }
    __syncthreads();

    // ---- layer 3: 64 -> 4, + residual x, write output
    if (tid < 64) {
        const int n = tid;
        float a3[4];
#pragma unroll
        for (int d = 0; d < ND; d++) a3[d] = out3_b[d];
        for (int k = 0; k < NH; k++) {
            float mv = m2_s[n * 65 + k];
#pragma unroll
            for (int d = 0; d < ND; d++) a3[d] += out3_w[d * NH + k] * mv;
        }
        const float* x = inputs + (((size_t)b * NN + n) * NT + t) * ND;
        float* op = out + (((size_t)b * NN + n) * TO + t) * ND;
#pragma unroll
        for (int d = 0; d < ND; d++) op[d] = x[d] + a3[d];
    }
}

// ---------------------------------------------------------------------------
extern "C" void kernel_launch(void* const* d_in, const int* in_sizes, int n_in,
                              void* d_out, int out_size) {
    const float* inputs   = (const float*)d_in[0];
    const float* rel_type = (const float*)d_in[1];
    const float* fc1_w    = (const float*)d_in[4];
    const float* fc1_b    = (const float*)d_in[5];
    const float* fc2_w    = (const float*)d_in[6];
    const float* fc2_b    = (const float*)d_in[7];
    const float* out1_w   = (const float*)d_in[8];
    const float* out1_b   = (const float*)d_in[9];
    const float* out2_w   = (const float*)d_in[10];
    const float* out2_b   = (const float*)d_in[11];
    const float* out3_w   = (const float*)d_in[12];
    const float* out3_b   = (const float*)d_in[13];
    float* out = (float*)d_out;

    const int n_embed = NNODES * NH;
    k_node_embed<<<(n_embed + 255) / 256, 256>>>(inputs, fc1_w, fc1_b, out1_w, out2_w);

    k_edge_mma<<<GRID, 256>>>(rel_type, fc2_w, fc2_b);

    k_node_mlp<<<NBT, 256>>>(inputs, out1_b, out2_b, out3_w, out3_b, out);
}